// round 6
// baseline (speedup 1.0000x reference)
#include <cuda_runtime.h>
#include <math.h>
#include <stdint.h>

#define H     128
#define NB    16384
#define NPG   26
#define EPG   52
#define NCL   7
#define NTOT  (NB*NPG)      // 425984
#define NEDGE (NB*EPG)      // 851968

// ------------- scratch: device globals (no runtime allocation) -------------
__device__ float g_h[NTOT*H];        // node features (in-place per layer)
__device__ float g_t[NTOT*14];       // [n*14+c]: c<7 -> h@aWl, c>=7 -> h@aWr
__device__ float g_x2[NB*NCL*H];     // pooled cluster features (in-place)
__device__ float g_pm[NB*H];         // per-graph mean of clusters
__device__ float g_linkpart[NB];
__device__ float g_entpart[NB];

// ================= K1: atom encoder =================
__global__ void k_encode(const int* __restrict__ x, const float* __restrict__ emb) {
    const int tid = threadIdx.x;
    const int n0  = blockIdx.x * 32;
    __shared__ int sx[32 * 9];
    for (int i = tid; i < 32 * 9; i += 128) sx[i] = x[(size_t)n0 * 9 + i];
    __syncthreads();
    for (int nn = 0; nn < 32; nn++) {
        float acc = 0.f;
        #pragma unroll
        for (int f = 0; f < 9; f++) {
            int v = sx[nn * 9 + f];
            acc += emb[((size_t)f * 119 + v) * 128 + tid];
        }
        g_h[(size_t)(n0 + nn) * 128 + tid] = acc;
    }
}

// ================= tf32 mma.sync helper (verified layout) =================
__device__ __forceinline__ void mma_tf32(float* d, const uint32_t* a,
                                         uint32_t b0, uint32_t b1) {
    asm volatile(
        "mma.sync.aligned.m16n8k8.row.col.f32.tf32.tf32.f32 "
        "{%0,%1,%2,%3}, {%4,%5,%6,%7}, {%8,%9}, {%0,%1,%2,%3};\n"
        : "+f"(d[0]), "+f"(d[1]), "+f"(d[2]), "+f"(d[3])
        : "r"(a[0]), "r"(a[1]), "r"(a[2]), "r"(a[3]), "r"(b0), "r"(b1));
}

#define FP 132   // smem pitch (floats)

// ================= K2: fused mean + GEMM + bias/BN/ReLU/residual =================
// Block = 2 graphs = 52 real rows (padded to 64 for MMA).
// h' = bn([mean||h] @ [Wl;Wr] + bl) + relu + h, written in place on g_h.
__global__ __launch_bounds__(256)
void k_fused(const int* __restrict__ ei,
             const float* __restrict__ Wl, const float* __restrict__ Wr,
             const float* __restrict__ bl,
             const float* __restrict__ bng, const float* __restrict__ bnb,
             const float* __restrict__ bnm, const float* __restrict__ bnv)
{
    extern __shared__ float smem[];
    float* sH = smem;               // 64 x FP (h rows, residual source)
    float* sM = smem + 64*FP;       // 64 x FP (neighbor means)
    float* sW = smem + 2*64*FP;     // 64 x FP (weight K-chunk)
    __shared__ int   sse[104], sde[104], sdeg[52], sstart[2][27], soffs[52], ssrt[104];
    __shared__ float srdeg[52], sscale[128], sshift[128];

    const int tid = threadIdx.x;
    const int g0  = blockIdx.x * 2;
    const size_t r0 = (size_t)g0 * NPG;

    // load 52 rows of h; zero pad rows 52..63 of sH and sM
    for (int i = tid; i < 52*32; i += 256) {
        int r = i >> 5, c = (i & 31) * 4;
        *(float4*)&sH[r*FP + c] = *(const float4*)(g_h + (r0 + r)*128 + c);
    }
    for (int i = tid; i < 12*32; i += 256) {
        int r = 52 + (i >> 5), c = (i & 31) * 4;
        float4 z = make_float4(0.f, 0.f, 0.f, 0.f);
        *(float4*)&sH[r*FP + c] = z;
        *(float4*)&sM[r*FP + c] = z;
    }
    if (tid < 52)  sdeg[tid] = 0;
    if (tid < 128) {
        float sc = bng[tid] * rsqrtf(bnv[tid] + 1e-5f);
        sscale[tid] = sc;
        sshift[tid] = bnb[tid] + sc * (bl[tid] - bnm[tid]);
    }
    __syncthreads();
    if (tid < 104) {
        int q = tid / 52, e = tid - q*52, g = g0 + q;
        int s = ei[(size_t)g*EPG + e]                 - g*NPG;
        int d = ei[(size_t)NEDGE + (size_t)g*EPG + e] - g*NPG;
        sse[tid] = s; sde[tid] = d;
        atomicAdd(&sdeg[q*26 + d], 1);
    }
    __syncthreads();
    if (tid < 2) {
        int acc = 0;
        for (int n = 0; n < 26; n++) { sstart[tid][n] = acc; acc += sdeg[tid*26 + n]; }
        sstart[tid][26] = acc;
    }
    if (tid < 52) srdeg[tid] = 1.f / fmaxf((float)sdeg[tid], 1.f);
    __syncthreads();
    if (tid < 52) soffs[tid] = sstart[tid/26][tid%26];
    __syncthreads();
    if (tid < 104) {
        int q = tid / 52;
        int pos = atomicAdd(&soffs[q*26 + sde[tid]], 1);
        ssrt[q*52 + pos] = sse[tid];
    }
    __syncthreads();
    // mean via sorted edge lists: short independent register-accumulated runs
    {
        const int q = tid >> 7, c = tid & 127;
        const int* srt = ssrt + q*52;
        #pragma unroll 2
        for (int n = 0; n < 26; n++) {
            float acc = 0.f;
            int b = sstart[q][n], e2 = sstart[q][n+1];
            for (int j = b; j < e2; j++) acc += sH[(q*26 + srt[j])*FP + c];
            sM[(q*26 + n)*FP + c] = acc * srdeg[q*26 + n];
        }
    }

    // GEMM: 8 warps = 2(M) x 4(N); warp tile 32x32
    const int lane = tid & 31, warp = tid >> 5;
    const int gid = lane >> 2, tig = lane & 3;
    const int m0  = (warp & 1) * 32;
    const int n0w = (warp >> 1) * 32;
    float d[2][4][4] = {};

    #pragma unroll
    for (int phase = 0; phase < 4; phase++) {
        const float* Wop = (phase < 2) ? Wl : Wr;
        const int kc = phase & 1;
        const float* sA = (phase < 2) ? sM : sH;
        __syncthreads();   // prior phase done with sW (phase 0: mean done)
        for (int i = tid; i < 64*32; i += 256) {
            int r = i >> 5, c = (i & 31) * 4;
            *(float4*)&sW[r*FP + c] = *(const float4*)(Wop + (size_t)(kc*64 + r)*128 + c);
        }
        __syncthreads();
        #pragma unroll
        for (int ks = 0; ks < 8; ks++) {
            const int kk = ks * 8;
            uint32_t a[2][4];
            #pragma unroll
            for (int mi = 0; mi < 2; mi++) {
                const float* ap = sA + (m0 + mi*16 + gid)*FP + kc*64 + kk + tig;
                a[mi][0] = __float_as_uint(ap[0]);
                a[mi][1] = __float_as_uint(ap[8*FP]);
                a[mi][2] = __float_as_uint(ap[4]);
                a[mi][3] = __float_as_uint(ap[8*FP + 4]);
            }
            const float* bp = sW + (kk + tig)*FP + n0w + gid;
            #pragma unroll
            for (int nj = 0; nj < 4; nj++) {
                uint32_t b0 = __float_as_uint(bp[nj*8]);
                uint32_t b1 = __float_as_uint(bp[nj*8 + 4*FP]);
                mma_tf32(d[0][nj], a[0], b0, b1);
                mma_tf32(d[1][nj], a[1], b0, b1);
            }
        }
    }

    // epilogue: bn + relu + residual; only real rows (<52) written
    #pragma unroll
    for (int mi = 0; mi < 2; mi++)
        #pragma unroll
        for (int half = 0; half < 2; half++) {
            const int row = m0 + mi*16 + gid + half*8;
            if (row < 52) {
                float* orow = g_h + (r0 + row) * 128;
                #pragma unroll
                for (int nj = 0; nj < 4; nj++) {
                    const int col = n0w + nj*8 + tig*2;
                    float v0 = d[mi][nj][half*2 + 0] * sscale[col]     + sshift[col];
                    float v1 = d[mi][nj][half*2 + 1] * sscale[col + 1] + sshift[col + 1];
                    v0 = fmaxf(v0, 0.f); v1 = fmaxf(v1, 0.f);
                    v0 += sH[row*FP + col];
                    v1 += sH[row*FP + col + 1];
                    *(float2*)(orow + col) = make_float2(v0, v1);
                }
            }
        }
}

// ================= K3: skinny products T1 = h@aWl, T2 = h@aWr (warp/node) =================
__global__ void k_slogT(const float* __restrict__ aWl, const float* __restrict__ aWr) {
    __shared__ float sWl[128 * NCL], sWr[128 * NCL];
    const int tid = threadIdx.x;  // 256
    for (int i = tid; i < 128 * NCL; i += 256) { sWl[i] = aWl[i]; sWr[i] = aWr[i]; }
    __syncthreads();
    const int warp = tid >> 5, lane = tid & 31;
    const int n = blockIdx.x * 8 + warp;     // grid = NTOT/8 exactly
    const float* hrow = g_h + (size_t)n * 128;
    float h[4];
    #pragma unroll
    for (int j = 0; j < 4; j++) h[j] = hrow[lane + 32*j];
    #pragma unroll
    for (int c = 0; c < NCL; c++) {
        float p1 = 0.f, p2 = 0.f;
        #pragma unroll
        for (int j = 0; j < 4; j++) {
            int k = lane + 32*j;
            p1 += h[j] * sWl[k*NCL + c];
            p2 += h[j] * sWr[k*NCL + c];
        }
        #pragma unroll
        for (int off = 16; off > 0; off >>= 1) {
            p1 += __shfl_down_sync(0xffffffffu, p1, off);
            p2 += __shfl_down_sync(0xffffffffu, p2, off);
        }
        if (lane == 0) {
            g_t[(size_t)n*14 + c]     = p1;
            g_t[(size_t)n*14 + 7 + c] = p2;
        }
    }
}

// ================= K4: per-graph logits-agg + softmax + pooling + losses =================
__global__ void k_pool(const int* __restrict__ ei, const float* __restrict__ abl) {
    __shared__ float sh[NPG * H];
    __shared__ float t1[NPG*NCL], t2[NPG*NCL], ssl[NPG*NCL], sd[NPG*NCL];
    __shared__ float adj[NPG * NPG];
    __shared__ int   se[EPG], de[EPG], degi[NPG];
    __shared__ float red[128], red2[128];
    const int g = blockIdx.x, tid = threadIdx.x;  // 128
    const float* hg = g_h + (size_t)g * NPG * H;
    for (int i = tid; i < NPG * H; i += 128) sh[i] = hg[i];
    for (int i = tid; i < NPG * 14; i += 128) {
        int n = i / 14, c = i - n*14;
        float v = g_t[(size_t)g*NPG*14 + i];
        if (c < 7) t1[n*7 + c] = v; else t2[n*7 + (c-7)] = v;
    }
    for (int i = tid; i < NPG * NPG; i += 128) adj[i] = 0.f;
    for (int i = tid; i < NPG * NCL; i += 128) ssl[i] = 0.f;
    if (tid < NPG) degi[tid] = 0;
    if (tid < EPG) {
        se[tid] = ei[(size_t)g*EPG + tid]                 - g*NPG;
        de[tid] = ei[(size_t)NEDGE + (size_t)g*EPG + tid] - g*NPG;
    }
    __syncthreads();
    if (tid < EPG) {
        atomicAdd(&degi[de[tid]], 1);
        atomicAdd(&adj[se[tid]*NPG + de[tid]], 1.f);
        #pragma unroll
        for (int c = 0; c < NCL; c++)
            atomicAdd(&ssl[de[tid]*NCL + c], t1[se[tid]*NCL + c]);
    }
    __syncthreads();
    for (int i = tid; i < NPG * NCL; i += 128) {
        int n = i / NCL;
        ssl[i] = ssl[i] / fmaxf((float)degi[n], 1.f) + t2[i] + abl[i - n*NCL];
    }
    __syncthreads();
    float ent_local = 0.f;
    if (tid < NPG) {
        float v[NCL], mx = -1e30f;
        #pragma unroll
        for (int c = 0; c < NCL; c++) { v[c] = ssl[tid*NCL + c]; mx = fmaxf(mx, v[c]); }
        float s = 0.f;
        #pragma unroll
        for (int c = 0; c < NCL; c++) { v[c] = expf(v[c] - mx); s += v[c]; }
        float inv = 1.f / s;
        #pragma unroll
        for (int c = 0; c < NCL; c++) {
            float p = v[c] * inv;
            sd[tid*NCL + c] = p;
            ent_local += -p * logf(p + 1e-15f);
        }
    }
    __syncthreads();
    float* x2g = g_x2 + (size_t)g * NCL * H;
    #pragma unroll
    for (int c = 0; c < NCL; c++) {
        float a = 0.f;
        #pragma unroll
        for (int n = 0; n < NPG; n++) a += sd[n*NCL + c] * sh[n*128 + tid];
        x2g[c*128 + tid] = a;
    }
    float link_local = 0.f;
    for (int p = tid; p < NPG * NPG; p += 128) {
        int n = p / NPG, m = p - NPG*n;
        float ss = 0.f;
        #pragma unroll
        for (int c = 0; c < NCL; c++) ss += sd[n*NCL + c] * sd[m*NCL + c];
        float dd = adj[p] - ss;
        link_local += dd * dd;
    }
    red[tid] = link_local; red2[tid] = ent_local;
    __syncthreads();
    for (int s = 64; s > 0; s >>= 1) {
        if (tid < s) { red[tid] += red[tid + s]; red2[tid] += red2[tid + s]; }
        __syncthreads();
    }
    if (tid == 0) { g_linkpart[g] = red[0]; g_entpart[g] = red2[0]; }
}

// ================= K5: pooled-layer GEMM (R4-proven) =================
#define WPITCH 132
#define APITCH 68
__global__ __launch_bounds__(256)
void k_gemm_pool(const float* __restrict__ Wl, const float* __restrict__ Wr,
                 const float* __restrict__ bl,
                 const float* __restrict__ bng, const float* __restrict__ bnb,
                 const float* __restrict__ bnm, const float* __restrict__ bnv)
{
    extern __shared__ float smem[];
    float* sW = smem;
    float* sA = smem + 128*WPITCH;
    __shared__ float sscale[128], sshift[128];
    const int tid  = threadIdx.x;
    const int row0 = blockIdx.x * 128;
    if (tid < 128) {
        float sc = bng[tid] * rsqrtf(bnv[tid] + 1e-5f);
        sscale[tid] = sc;
        sshift[tid] = bnb[tid] + sc * (bl[tid] - bnm[tid]);
    }
    const int lane = tid & 31, warp = tid >> 5;
    const int gid = lane >> 2, tig = lane & 3;
    const int wr0 = (warp & 3) * 32;
    const int wc0 = (warp >> 2) * 64;
    float d[2][8][4] = {};
    #pragma unroll
    for (int phase = 0; phase < 2; phase++) {
        const float* Wop = phase == 0 ? Wl : Wr;
        __syncthreads();
        for (int i = tid; i < 128*32; i += 256) {
            int r = i >> 5, c = (i & 31) * 4;
            *(float4*)&sW[r*WPITCH + c] = *(const float4*)(Wop + (size_t)r*128 + c);
        }
        #pragma unroll
        for (int kc = 0; kc < 2; kc++) {
            __syncthreads();
            for (int i = tid; i < 128*16; i += 256) {
                int r = i >> 4, c = (i & 15) * 4;
                int grow = row0 + r;
                const float* ap = (phase == 0) ? (g_pm + (size_t)(grow/7)*128)
                                               : (g_x2 + (size_t)grow*128);
                *(float4*)&sA[r*APITCH + c] = *(const float4*)(ap + kc*64 + c);
            }
            __syncthreads();
            #pragma unroll
            for (int ks = 0; ks < 8; ks++) {
                const int kk = ks * 8;
                uint32_t a[2][4];
                #pragma unroll
                for (int mi = 0; mi < 2; mi++) {
                    const float* ap = sA + (wr0 + mi*16 + gid)*APITCH + kk + tig;
                    a[mi][0] = __float_as_uint(ap[0]);
                    a[mi][1] = __float_as_uint(ap[8*APITCH]);
                    a[mi][2] = __float_as_uint(ap[4]);
                    a[mi][3] = __float_as_uint(ap[8*APITCH + 4]);
                }
                const float* bp = sW + (kc*64 + kk + tig)*WPITCH + wc0 + gid;
                #pragma unroll
                for (int nj = 0; nj < 8; nj++) {
                    uint32_t b0 = __float_as_uint(bp[nj*8]);
                    uint32_t b1 = __float_as_uint(bp[nj*8 + 4*WPITCH]);
                    mma_tf32(d[0][nj], a[0], b0, b1);
                    mma_tf32(d[1][nj], a[1], b0, b1);
                }
            }
        }
    }
    #pragma unroll
    for (int mi = 0; mi < 2; mi++)
        #pragma unroll
        for (int half = 0; half < 2; half++) {
            const int row = wr0 + mi*16 + gid + half*8;
            float* orow = g_x2 + (size_t)(row0 + row) * 128;
            #pragma unroll
            for (int nj = 0; nj < 8; nj++) {
                const int col = wc0 + nj*8 + tig*2;
                float2 res = *(float2*)(orow + col);
                float v0 = d[mi][nj][half*2 + 0] * sscale[col]     + sshift[col];
                float v1 = d[mi][nj][half*2 + 1] * sscale[col + 1] + sshift[col + 1];
                *(float2*)(orow + col) = make_float2(v0 + res.x, v1 + res.y);
            }
        }
}

// ================= K6: per-graph mean of clusters =================
__global__ void k_pmean() {
    int idx = blockIdx.x * 256 + threadIdx.x;
    int g = idx >> 7, col = idx & 127;
    const float* xg = g_x2 + (size_t)g * NCL * H + col;
    float a = 0.f;
    #pragma unroll
    for (int c = 0; c < NCL; c++) a += xg[c * 128];
    g_pm[idx] = a * (1.f / 7.f);
}

// ================= K7: readout =================
__global__ void k_readout(const float* __restrict__ linW, const float* __restrict__ linb,
                          float* __restrict__ out) {
    const int g = blockIdx.x, tid = threadIdx.x;  // 128
    const float* xg = g_x2 + (size_t)g * NCL * H;
    float v = 0.f;
    #pragma unroll
    for (int c = 0; c < NCL; c++) v += xg[c * 128 + tid];
    v *= (1.f / 7.f);
    __shared__ float red[128];
    red[tid] = v * linW[tid];
    __syncthreads();
    for (int s = 64; s > 0; s >>= 1) {
        if (tid < s) red[tid] += red[tid + s];
        __syncthreads();
    }
    if (tid == 0) out[g] = 1.f / (1.f + expf(-(red[0] + linb[0])));
}

// ================= K8: deterministic loss reduction =================
__global__ void k_reduce(float* __restrict__ out) {
    __shared__ float s1[1024], s2[1024];
    const int tid = threadIdx.x;
    float a = 0.f, b = 0.f;
    for (int i = tid; i < NB; i += 1024) { a += g_linkpart[i]; b += g_entpart[i]; }
    s1[tid] = a; s2[tid] = b;
    __syncthreads();
    for (int s = 512; s > 0; s >>= 1) {
        if (tid < s) { s1[tid] += s1[tid + s]; s2[tid] += s2[tid + s]; }
        __syncthreads();
    }
    if (tid == 0) {
        out[NB]     = sqrtf(s1[0]) / 11075584.f;   // nb * 26 * 26
        out[NB + 1] = s2[0] / (float)NTOT;
    }
}

extern "C" void kernel_launch(void* const* d_in, const int* in_sizes, int n_in,
                              void* d_out, int out_size) {
    (void)in_sizes; (void)n_in; (void)out_size;
    const int*   x    = (const int*)  d_in[0];
    const int*   ei   = (const int*)  d_in[1];
    const float* emb  = (const float*)d_in[3];
    const float* cWl  = (const float*)d_in[4];
    const float* cbl  = (const float*)d_in[5];
    const float* cWr  = (const float*)d_in[6];
    const float* bng  = (const float*)d_in[7];
    const float* bnb  = (const float*)d_in[8];
    const float* bnm  = (const float*)d_in[9];
    const float* bnv  = (const float*)d_in[10];
    const float* aWl  = (const float*)d_in[11];
    const float* abl  = (const float*)d_in[12];
    const float* aWr  = (const float*)d_in[13];
    const float* linW = (const float*)d_in[14];
    const float* linb = (const float*)d_in[15];
    float* out = (float*)d_out;

    const int fused_smem = 3 * 64 * FP * 4;                  // 101376
    const int pool_smem  = (128*WPITCH + 128*APITCH) * 4;    // 102400
    cudaFuncSetAttribute(k_fused, cudaFuncAttributeMaxDynamicSharedMemorySize, fused_smem);
    cudaFuncSetAttribute(k_gemm_pool, cudaFuncAttributeMaxDynamicSharedMemorySize, pool_smem);

    k_encode<<<NTOT / 32, 128>>>(x, emb);

    for (int li = 0; li < 2; li++) {
        k_fused<<<NB / 2, 256, fused_smem>>>(ei,
            cWl + li*16384, cWr + li*16384, cbl + li*128,
            bng + li*128, bnb + li*128, bnm + li*128, bnv + li*128);
    }

    k_slogT<<<NTOT / 8, 256>>>(aWl, aWr);
    k_pool<<<NB, 128>>>(ei, abl);

    for (int li = 2; li < 4; li++) {
        k_pmean<<<NB * 128 / 256, 256>>>();
        k_gemm_pool<<<NB * NCL / 128, 256, pool_smem>>>(
            cWl + li*16384, cWr + li*16384, cbl + li*128,
            bng + li*128, bnb + li*128, bnm + li*128, bnv + li*128);
    }

    k_readout<<<NB, 128>>>(linW, linb, out);
    k_reduce<<<1, 1024>>>(out);
}

// round 7
// speedup vs baseline: 1.1052x; 1.1052x over previous
#include <cuda_runtime.h>
#include <math.h>
#include <stdint.h>

#define H     128
#define NB    16384
#define NPG   26
#define EPG   52
#define NCL   7
#define NTOT  (NB*NPG)      // 425984
#define NEDGE (NB*EPG)      // 851968

// ------------- scratch: device globals (no runtime allocation) -------------
__device__ float g_h[NTOT*H];        // node features (in-place per layer)
__device__ float g_mean[NTOT*H];     // neighbor means
__device__ float g_t[NTOT*14];       // [n*14+c]: c<7 -> h@aWl, c>=7 -> h@aWr
__device__ float g_x2[NB*NCL*H];     // pooled cluster features (in-place)
__device__ float g_pm[NB*H];         // per-graph mean of clusters
__device__ float g_linkpart[NB];
__device__ float g_entpart[NB];

// ================= K1: atom encoder (emb column-slice resident in smem) =================
// grid (416, 4), 256 threads; block = 1024 nodes x 32-column slice.
__global__ void k_encode2(const int* __restrict__ x, const float* __restrict__ emb) {
    extern __shared__ float s_emb[];            // 9*119*32 floats = 137KB
    const int cg   = blockIdx.y;
    const int lane = threadIdx.x & 31;
    const int sub  = threadIdx.x >> 5;
    for (int i = threadIdx.x; i < 9*119*32; i += 256)
        s_emb[i] = emb[(size_t)(i >> 5) * 128 + cg*32 + (i & 31)];
    __syncthreads();
    const int n0 = blockIdx.x * 1024;
    for (int n = n0 + sub; n < n0 + 1024; n += 8) {
        float acc = 0.f;
        #pragma unroll
        for (int f = 0; f < 9; f++) {
            int v = __ldg(&x[(size_t)n*9 + f]);
            acc += s_emb[(f*119 + v)*32 + lane];
        }
        g_h[(size_t)n*128 + cg*32 + lane] = acc;
    }
}

// ================= K2: neighbor-mean via CSR counting sort (1 graph/block) =================
__global__ __launch_bounds__(128)
void k_agg2(const int* __restrict__ ei) {
    __shared__ float sh[NPG * H];               // 13.3KB
    __shared__ int   se[EPG], sde[EPG], sdeg[NPG], sstart[NPG+1], soffs[NPG], ssrt[EPG];
    __shared__ float srdeg[NPG];
    const int g = blockIdx.x, tid = threadIdx.x;
    const float* hg = g_h + (size_t)g * NPG * H;
    for (int i = tid; i < NPG*32; i += 128)
        *(float4*)&sh[i*4] = *(const float4*)(hg + (size_t)i*4);
    if (tid < NPG) sdeg[tid] = 0;
    __syncthreads();
    if (tid < EPG) {
        int s = ei[(size_t)g*EPG + tid]                 - g*NPG;
        int d = ei[(size_t)NEDGE + (size_t)g*EPG + tid] - g*NPG;
        se[tid] = s; sde[tid] = d;
        atomicAdd(&sdeg[d], 1);
    }
    __syncthreads();
    if (tid == 0) {
        int acc = 0;
        #pragma unroll
        for (int n = 0; n < NPG; n++) { sstart[n] = acc; acc += sdeg[n]; }
        sstart[NPG] = acc;
    }
    if (tid < NPG) srdeg[tid] = 1.f / fmaxf((float)sdeg[tid], 1.f);
    __syncthreads();
    if (tid < NPG) soffs[tid] = sstart[tid];
    __syncthreads();
    if (tid < EPG) {
        int pos = atomicAdd(&soffs[sde[tid]], 1);
        ssrt[pos] = se[tid];
    }
    __syncthreads();
    float* mg = g_mean + (size_t)g * NPG * H;
    const int c = tid;   // thread owns column c
    #pragma unroll 2
    for (int n = 0; n < NPG; n++) {
        float acc = 0.f;
        int b = sstart[n], e2 = sstart[n+1];
        for (int j = b; j < e2; j++) acc += sh[ssrt[j]*H + c];
        mg[(size_t)n*H + c] = acc * srdeg[n];
    }
}

// ================= tf32 mma.sync helper (verified layout) =================
__device__ __forceinline__ void mma_tf32(float* d, const uint32_t* a,
                                         uint32_t b0, uint32_t b1) {
    asm volatile(
        "mma.sync.aligned.m16n8k8.row.col.f32.tf32.tf32.f32 "
        "{%0,%1,%2,%3}, {%4,%5,%6,%7}, {%8,%9}, {%0,%1,%2,%3};\n"
        : "+f"(d[0]), "+f"(d[1]), "+f"(d[2]), "+f"(d[3])
        : "r"(a[0]), "r"(a[1]), "r"(a[2]), "r"(a[3]), "r"(b0), "r"(b1));
}

#define WPITCH 132
#define APITCH 68

// ================= K3: tensor-core GEMM + bias/BN/(ReLU)/residual (R4-proven) =================
template<int RELU, int POOLED>
__global__ __launch_bounds__(256)
void k_gemm_tc(const float* __restrict__ Wl, const float* __restrict__ Wr,
               const float* __restrict__ bl,
               const float* __restrict__ bng, const float* __restrict__ bnb,
               const float* __restrict__ bnm, const float* __restrict__ bnv)
{
    extern __shared__ float smem[];
    float* sW = smem;                  // 128 x WPITCH
    float* sA = smem + 128*WPITCH;     // 128 x APITCH (64-wide k chunk)
    __shared__ float sscale[128], sshift[128];

    const int tid  = threadIdx.x;
    const int row0 = blockIdx.x * 128;
    const float* Am = POOLED ? g_pm : g_mean;
    float*       Ah = POOLED ? g_x2 : g_h;

    if (tid < 128) {
        float sc = bng[tid] * rsqrtf(bnv[tid] + 1e-5f);
        sscale[tid] = sc;
        sshift[tid] = bnb[tid] + sc * (bl[tid] - bnm[tid]);
    }

    const int lane = tid & 31, warp = tid >> 5;
    const int gid = lane >> 2, tig = lane & 3;
    const int wr0 = (warp & 3) * 32;
    const int wc0 = (warp >> 2) * 64;
    float d[2][8][4] = {};

    #pragma unroll
    for (int phase = 0; phase < 2; phase++) {
        const float* Wop = phase == 0 ? Wl : Wr;
        __syncthreads();
        for (int i = tid; i < 128*32; i += 256) {
            int r = i >> 5, c = (i & 31) * 4;
            *(float4*)&sW[r*WPITCH + c] = *(const float4*)(Wop + (size_t)r*128 + c);
        }
        #pragma unroll
        for (int kc = 0; kc < 2; kc++) {
            __syncthreads();
            for (int i = tid; i < 128*16; i += 256) {
                int r = i >> 4, c = (i & 15) * 4;
                int grow = row0 + r;
                const float* ap;
                if (phase == 0) {
                    int mrow = POOLED ? (grow / 7) : grow;
                    ap = Am + (size_t)mrow * 128;
                } else {
                    ap = Ah + (size_t)grow * 128;
                }
                *(float4*)&sA[r*APITCH + c] = *(const float4*)(ap + kc*64 + c);
            }
            __syncthreads();
            #pragma unroll
            for (int ks = 0; ks < 8; ks++) {
                const int kk = ks * 8;
                uint32_t a[2][4];
                #pragma unroll
                for (int mi = 0; mi < 2; mi++) {
                    const float* ap = sA + (wr0 + mi*16 + gid)*APITCH + kk + tig;
                    a[mi][0] = __float_as_uint(ap[0]);
                    a[mi][1] = __float_as_uint(ap[8*APITCH]);
                    a[mi][2] = __float_as_uint(ap[4]);
                    a[mi][3] = __float_as_uint(ap[8*APITCH + 4]);
                }
                const float* bp = sW + (kc*64 + kk + tig)*WPITCH + wc0 + gid;
                #pragma unroll
                for (int nj = 0; nj < 8; nj++) {
                    uint32_t b0 = __float_as_uint(bp[nj*8]);
                    uint32_t b1 = __float_as_uint(bp[nj*8 + 4*WPITCH]);
                    mma_tf32(d[0][nj], a[0], b0, b1);
                    mma_tf32(d[1][nj], a[1], b0, b1);
                }
            }
        }
    }

    #pragma unroll
    for (int mi = 0; mi < 2; mi++)
        #pragma unroll
        for (int half = 0; half < 2; half++) {
            const int row = wr0 + mi*16 + gid + half*8;
            float* orow = Ah + (size_t)(row0 + row) * 128;
            #pragma unroll
            for (int nj = 0; nj < 8; nj++) {
                const int col = wc0 + nj*8 + tig*2;
                float2 res = *(float2*)(orow + col);
                float v0 = d[mi][nj][half*2 + 0] * sscale[col]     + sshift[col];
                float v1 = d[mi][nj][half*2 + 1] * sscale[col + 1] + sshift[col + 1];
                if (RELU) { v0 = fmaxf(v0, 0.f); v1 = fmaxf(v1, 0.f); }
                *(float2*)(orow + col) = make_float2(v0 + res.x, v1 + res.y);
            }
        }
}

// ================= K4: skinny products T=[h@aWl | h@aWr] (thread per node) =================
__global__ __launch_bounds__(256)
void k_slogT2(const float* __restrict__ aWl, const float* __restrict__ aWr) {
    __shared__ float sW[128*16];   // [k][c]: c<7 aWl, 7..13 aWr, 14/15 zero
    const int tid = threadIdx.x;
    for (int i = tid; i < 128*16; i += 256) {
        int k = i >> 4, c = i & 15;
        float v = 0.f;
        if (c < 7)       v = aWl[k*NCL + c];
        else if (c < 14) v = aWr[k*NCL + (c - 7)];
        sW[i] = v;
    }
    __syncthreads();
    const int n = blockIdx.x * 256 + tid;
    const float4* row = (const float4*)(g_h + (size_t)n * 128);
    float acc[14];
    #pragma unroll
    for (int c = 0; c < 14; c++) acc[c] = 0.f;
    #pragma unroll 8
    for (int i = 0; i < 32; i++) {
        float4 hv = row[i];
        const float* w = sW + i*4*16;
        #pragma unroll
        for (int c = 0; c < 14; c++)
            acc[c] += hv.x*w[c] + hv.y*w[16+c] + hv.z*w[32+c] + hv.w*w[48+c];
    }
    float* t = g_t + (size_t)n * 14;
    #pragma unroll
    for (int c = 0; c < 14; c++) t[c] = acc[c];
}

// ================= K5: per-graph logits-agg + softmax + pooling + losses =================
__global__ void k_pool(const int* __restrict__ ei, const float* __restrict__ abl) {
    __shared__ float sh[NPG * H];
    __shared__ float t1[NPG*NCL], t2[NPG*NCL], ssl[NPG*NCL], sd[NPG*NCL];
    __shared__ float adj[NPG * NPG];
    __shared__ int   se[EPG], de[EPG], degi[NPG];
    __shared__ float red[128], red2[128];
    const int g = blockIdx.x, tid = threadIdx.x;  // 128
    const float* hg = g_h + (size_t)g * NPG * H;
    for (int i = tid; i < NPG * H; i += 128) sh[i] = hg[i];
    for (int i = tid; i < NPG * 14; i += 128) {
        int n = i / 14, c = i - n*14;
        float v = g_t[(size_t)g*NPG*14 + i];
        if (c < 7) t1[n*7 + c] = v; else t2[n*7 + (c-7)] = v;
    }
    for (int i = tid; i < NPG * NPG; i += 128) adj[i] = 0.f;
    for (int i = tid; i < NPG * NCL; i += 128) ssl[i] = 0.f;
    if (tid < NPG) degi[tid] = 0;
    if (tid < EPG) {
        se[tid] = ei[(size_t)g*EPG + tid]                 - g*NPG;
        de[tid] = ei[(size_t)NEDGE + (size_t)g*EPG + tid] - g*NPG;
    }
    __syncthreads();
    if (tid < EPG) {
        atomicAdd(&degi[de[tid]], 1);
        atomicAdd(&adj[se[tid]*NPG + de[tid]], 1.f);
        #pragma unroll
        for (int c = 0; c < NCL; c++)
            atomicAdd(&ssl[de[tid]*NCL + c], t1[se[tid]*NCL + c]);
    }
    __syncthreads();
    for (int i = tid; i < NPG * NCL; i += 128) {
        int n = i / NCL;
        ssl[i] = ssl[i] / fmaxf((float)degi[n], 1.f) + t2[i] + abl[i - n*NCL];
    }
    __syncthreads();
    float ent_local = 0.f;
    if (tid < NPG) {
        float v[NCL], mx = -1e30f;
        #pragma unroll
        for (int c = 0; c < NCL; c++) { v[c] = ssl[tid*NCL + c]; mx = fmaxf(mx, v[c]); }
        float s = 0.f;
        #pragma unroll
        for (int c = 0; c < NCL; c++) { v[c] = expf(v[c] - mx); s += v[c]; }
        float inv = 1.f / s;
        #pragma unroll
        for (int c = 0; c < NCL; c++) {
            float p = v[c] * inv;
            sd[tid*NCL + c] = p;
            ent_local += -p * logf(p + 1e-15f);
        }
    }
    __syncthreads();
    float* x2g = g_x2 + (size_t)g * NCL * H;
    #pragma unroll
    for (int c = 0; c < NCL; c++) {
        float a = 0.f;
        #pragma unroll
        for (int n = 0; n < NPG; n++) a += sd[n*NCL + c] * sh[n*128 + tid];
        x2g[c*128 + tid] = a;
    }
    float link_local = 0.f;
    for (int p = tid; p < NPG * NPG; p += 128) {
        int n = p / NPG, m = p - NPG*n;
        float ss = 0.f;
        #pragma unroll
        for (int c = 0; c < NCL; c++) ss += sd[n*NCL + c] * sd[m*NCL + c];
        float dd = adj[p] - ss;
        link_local += dd * dd;
    }
    red[tid] = link_local; red2[tid] = ent_local;
    __syncthreads();
    for (int s = 64; s > 0; s >>= 1) {
        if (tid < s) { red[tid] += red[tid + s]; red2[tid] += red2[tid + s]; }
        __syncthreads();
    }
    if (tid == 0) { g_linkpart[g] = red[0]; g_entpart[g] = red2[0]; }
}

// ================= K6: per-graph mean of clusters =================
__global__ void k_pmean() {
    int idx = blockIdx.x * 256 + threadIdx.x;
    int g = idx >> 7, col = idx & 127;
    const float* xg = g_x2 + (size_t)g * NCL * H + col;
    float a = 0.f;
    #pragma unroll
    for (int c = 0; c < NCL; c++) a += xg[c * 128];
    g_pm[idx] = a * (1.f / 7.f);
}

// ================= K7: readout =================
__global__ void k_readout(const float* __restrict__ linW, const float* __restrict__ linb,
                          float* __restrict__ out) {
    const int g = blockIdx.x, tid = threadIdx.x;  // 128
    const float* xg = g_x2 + (size_t)g * NCL * H;
    float v = 0.f;
    #pragma unroll
    for (int c = 0; c < NCL; c++) v += xg[c * 128 + tid];
    v *= (1.f / 7.f);
    __shared__ float red[128];
    red[tid] = v * linW[tid];
    __syncthreads();
    for (int s = 64; s > 0; s >>= 1) {
        if (tid < s) red[tid] += red[tid + s];
        __syncthreads();
    }
    if (tid == 0) out[g] = 1.f / (1.f + expf(-(red[0] + linb[0])));
}

// ================= K8: deterministic loss reduction =================
__global__ void k_reduce(float* __restrict__ out) {
    __shared__ float s1[1024], s2[1024];
    const int tid = threadIdx.x;
    float a = 0.f, b = 0.f;
    for (int i = tid; i < NB; i += 1024) { a += g_linkpart[i]; b += g_entpart[i]; }
    s1[tid] = a; s2[tid] = b;
    __syncthreads();
    for (int s = 512; s > 0; s >>= 1) {
        if (tid < s) { s1[tid] += s1[tid + s]; s2[tid] += s2[tid + s]; }
        __syncthreads();
    }
    if (tid == 0) {
        out[NB]     = sqrtf(s1[0]) / 11075584.f;   // nb * 26 * 26
        out[NB + 1] = s2[0] / (float)NTOT;
    }
}

extern "C" void kernel_launch(void* const* d_in, const int* in_sizes, int n_in,
                              void* d_out, int out_size) {
    (void)in_sizes; (void)n_in; (void)out_size;
    const int*   x    = (const int*)  d_in[0];
    const int*   ei   = (const int*)  d_in[1];
    const float* emb  = (const float*)d_in[3];
    const float* cWl  = (const float*)d_in[4];
    const float* cbl  = (const float*)d_in[5];
    const float* cWr  = (const float*)d_in[6];
    const float* bng  = (const float*)d_in[7];
    const float* bnb  = (const float*)d_in[8];
    const float* bnm  = (const float*)d_in[9];
    const float* bnv  = (const float*)d_in[10];
    const float* aWl  = (const float*)d_in[11];
    const float* abl  = (const float*)d_in[12];
    const float* aWr  = (const float*)d_in[13];
    const float* linW = (const float*)d_in[14];
    const float* linb = (const float*)d_in[15];
    float* out = (float*)d_out;

    const int enc_smem  = 9*119*32*4;                        // 137088
    const int gemm_smem = (128*WPITCH + 128*APITCH) * 4;     // 102400
    cudaFuncSetAttribute(k_encode2, cudaFuncAttributeMaxDynamicSharedMemorySize, enc_smem);
    cudaFuncSetAttribute(k_gemm_tc<1,0>, cudaFuncAttributeMaxDynamicSharedMemorySize, gemm_smem);
    cudaFuncSetAttribute(k_gemm_tc<0,1>, cudaFuncAttributeMaxDynamicSharedMemorySize, gemm_smem);

    k_encode2<<<dim3(416, 4), 256, enc_smem>>>(x, emb);

    for (int li = 0; li < 2; li++) {
        k_agg2<<<NB, 128>>>(ei);
        k_gemm_tc<1,0><<<NTOT / 128, 256, gemm_smem>>>(
            cWl + li*16384, cWr + li*16384, cbl + li*128,
            bng + li*128, bnb + li*128, bnm + li*128, bnv + li*128);
    }

    k_slogT2<<<NTOT / 256, 256>>>(aWl, aWr);
    k_pool<<<NB, 128>>>(ei, abl);

    for (int li = 2; li < 4; li++) {
        k_pmean<<<NB * 128 / 256, 256>>>();
        k_gemm_tc<0,1><<<NB * NCL / 128, 256, gemm_smem>>>(
            cWl + li*16384, cWr + li*16384, cbl + li*128,
            bng + li*128, bnb + li*128, bnm + li*128, bnv + li*128);
    }

    k_readout<<<NB, 128>>>(linW, linb, out);
    k_reduce<<<1, 1024>>>(out);
}

// round 8
// speedup vs baseline: 1.4137x; 1.2791x over previous
#include <cuda_runtime.h>
#include <math.h>
#include <stdint.h>

#define H     128
#define NB    16384
#define NPG   26
#define EPG   52
#define NCL   7
#define NTOT  (NB*NPG)      // 425984
#define NEDGE (NB*EPG)      // 851968

// ------------- scratch: device globals (no runtime allocation) -------------
__device__ float g_h[NTOT*H];        // node features (in-place per layer)
__device__ float g_mean[NTOT*H];     // neighbor means
__device__ float g_t[NTOT*14];       // [n*14+c]: c<7 -> h@aWl, c>=7 -> h@aWr
__device__ float g_x2[NB*NCL*H];     // pooled cluster features (in-place)
__device__ float g_pm[NB*H];         // per-graph mean of clusters
__device__ float g_linkpart[NB];
__device__ float g_entpart[NB];

// ================= K1: atom encoder (R2/R4-proven) =================
__global__ void k_encode(const int* __restrict__ x, const float* __restrict__ emb) {
    const int tid = threadIdx.x;
    const int n0  = blockIdx.x * 32;
    __shared__ int sx[32 * 9];
    for (int i = tid; i < 32 * 9; i += 128) sx[i] = x[(size_t)n0 * 9 + i];
    __syncthreads();
    for (int nn = 0; nn < 32; nn++) {
        float acc = 0.f;
        #pragma unroll
        for (int f = 0; f < 9; f++) {
            int v = sx[nn * 9 + f];
            acc += emb[((size_t)f * 119 + v) * 128 + tid];
        }
        g_h[(size_t)(n0 + nn) * 128 + tid] = acc;
    }
}

// ================= K2: neighbor-mean via CSR counting sort (R7-proven, 102us) =================
__global__ __launch_bounds__(128)
void k_agg2(const int* __restrict__ ei) {
    __shared__ float sh[NPG * H];
    __shared__ int   se[EPG], sde[EPG], sdeg[NPG], sstart[NPG+1], soffs[NPG], ssrt[EPG];
    __shared__ float srdeg[NPG];
    const int g = blockIdx.x, tid = threadIdx.x;
    const float* hg = g_h + (size_t)g * NPG * H;
    for (int i = tid; i < NPG*32; i += 128)
        *(float4*)&sh[i*4] = *(const float4*)(hg + (size_t)i*4);
    if (tid < NPG) sdeg[tid] = 0;
    __syncthreads();
    if (tid < EPG) {
        int s = ei[(size_t)g*EPG + tid]                 - g*NPG;
        int d = ei[(size_t)NEDGE + (size_t)g*EPG + tid] - g*NPG;
        se[tid] = s; sde[tid] = d;
        atomicAdd(&sdeg[d], 1);
    }
    __syncthreads();
    if (tid == 0) {
        int acc = 0;
        #pragma unroll
        for (int n = 0; n < NPG; n++) { sstart[n] = acc; acc += sdeg[n]; }
        sstart[NPG] = acc;
    }
    if (tid < NPG) srdeg[tid] = 1.f / fmaxf((float)sdeg[tid], 1.f);
    __syncthreads();
    if (tid < NPG) soffs[tid] = sstart[tid];
    __syncthreads();
    if (tid < EPG) {
        int pos = atomicAdd(&soffs[sde[tid]], 1);
        ssrt[pos] = se[tid];
    }
    __syncthreads();
    float* mg = g_mean + (size_t)g * NPG * H;
    const int c = tid;
    #pragma unroll 2
    for (int n = 0; n < NPG; n++) {
        float acc = 0.f;
        int b = sstart[n], e2 = sstart[n+1];
        for (int j = b; j < e2; j++) acc += sh[ssrt[j]*H + c];
        mg[(size_t)n*H + c] = acc * srdeg[n];
    }
}

// ================= tf32 mma.sync helper (verified layout) =================
__device__ __forceinline__ void mma_tf32(float* d, const uint32_t* a,
                                         uint32_t b0, uint32_t b1) {
    asm volatile(
        "mma.sync.aligned.m16n8k8.row.col.f32.tf32.tf32.f32 "
        "{%0,%1,%2,%3}, {%4,%5,%6,%7}, {%8,%9}, {%0,%1,%2,%3};\n"
        : "+f"(d[0]), "+f"(d[1]), "+f"(d[2]), "+f"(d[3])
        : "r"(a[0]), "r"(a[1]), "r"(a[2]), "r"(a[3]), "r"(b0), "r"(b1));
}

#define WPITCH 132
#define APITCH 68
#define TPITCH 17

// ================= K3: tensor-core GEMM + bias/BN/(ReLU)/residual =================
// COMPT=1 (li=1 only): also computes T = h_final @ [aWl|aWr] via an extra MMA pass.
template<int RELU, int POOLED, int COMPT>
__global__ __launch_bounds__(256, 2)
void k_gemm_tc(const float* __restrict__ Wl, const float* __restrict__ Wr,
               const float* __restrict__ bl,
               const float* __restrict__ bng, const float* __restrict__ bnb,
               const float* __restrict__ bnm, const float* __restrict__ bnv,
               const float* __restrict__ aWl, const float* __restrict__ aWr)
{
    extern __shared__ float smem[];
    float* sW = smem;                  // 128 x WPITCH (weights; later h_final for COMPT)
    float* sA = smem + 128*WPITCH;     // 128 x APITCH (64-wide k chunk)
    __shared__ float sscale[128], sshift[128];
    __shared__ float sW2[COMPT ? 128*TPITCH : 1];

    const int tid  = threadIdx.x;
    const int row0 = blockIdx.x * 128;
    const float* Am = POOLED ? g_pm : g_mean;
    float*       Ah = POOLED ? g_x2 : g_h;

    if (tid < 128) {
        float sc = bng[tid] * rsqrtf(bnv[tid] + 1e-5f);
        sscale[tid] = sc;
        sshift[tid] = bnb[tid] + sc * (bl[tid] - bnm[tid]);
    }
    if (COMPT) {
        for (int i = tid; i < 128*16; i += 256) {
            int k = i >> 4, c = i & 15;
            float v = 0.f;
            if (c < 7)       v = aWl[k*NCL + c];
            else if (c < 14) v = aWr[k*NCL + (c - 7)];
            sW2[k*TPITCH + c] = v;
        }
    }

    const int lane = tid & 31, warp = tid >> 5;
    const int gid = lane >> 2, tig = lane & 3;
    const int wr0 = (warp & 3) * 32;
    const int wc0 = (warp >> 2) * 64;
    float d[2][8][4] = {};

    #pragma unroll
    for (int phase = 0; phase < 2; phase++) {
        const float* Wop = phase == 0 ? Wl : Wr;
        __syncthreads();
        for (int i = tid; i < 128*32; i += 256) {
            int r = i >> 5, c = (i & 31) * 4;
            *(float4*)&sW[r*WPITCH + c] = *(const float4*)(Wop + (size_t)r*128 + c);
        }
        #pragma unroll
        for (int kc = 0; kc < 2; kc++) {
            __syncthreads();
            for (int i = tid; i < 128*16; i += 256) {
                int r = i >> 4, c = (i & 15) * 4;
                int grow = row0 + r;
                const float* ap;
                if (phase == 0) {
                    int mrow = POOLED ? (grow / 7) : grow;
                    ap = Am + (size_t)mrow * 128;
                } else {
                    ap = Ah + (size_t)grow * 128;
                }
                *(float4*)&sA[r*APITCH + c] = *(const float4*)(ap + kc*64 + c);
            }
            __syncthreads();
            #pragma unroll
            for (int ks = 0; ks < 8; ks++) {
                const int kk = ks * 8;
                uint32_t a[2][4];
                #pragma unroll
                for (int mi = 0; mi < 2; mi++) {
                    const float* ap = sA + (wr0 + mi*16 + gid)*APITCH + kk + tig;
                    a[mi][0] = __float_as_uint(ap[0]);
                    a[mi][1] = __float_as_uint(ap[8*APITCH]);
                    a[mi][2] = __float_as_uint(ap[4]);
                    a[mi][3] = __float_as_uint(ap[8*APITCH + 4]);
                }
                const float* bp = sW + (kc*64 + kk + tig)*WPITCH + wc0 + gid;
                #pragma unroll
                for (int nj = 0; nj < 8; nj++) {
                    uint32_t b0 = __float_as_uint(bp[nj*8]);
                    uint32_t b1 = __float_as_uint(bp[nj*8 + 4*WPITCH]);
                    mma_tf32(d[0][nj], a[0], b0, b1);
                    mma_tf32(d[1][nj], a[1], b0, b1);
                }
            }
        }
    }

    if (COMPT) __syncthreads();   // all warps done reading sW before overwrite

    // epilogue: bn + (relu) + residual; write global (+ sW tile if COMPT)
    #pragma unroll
    for (int mi = 0; mi < 2; mi++)
        #pragma unroll
        for (int half = 0; half < 2; half++) {
            const int row = wr0 + mi*16 + gid + half*8;
            float* orow = Ah + (size_t)(row0 + row) * 128;
            #pragma unroll
            for (int nj = 0; nj < 8; nj++) {
                const int col = wc0 + nj*8 + tig*2;
                float2 res = *(float2*)(orow + col);
                float v0 = d[mi][nj][half*2 + 0] * sscale[col]     + sshift[col];
                float v1 = d[mi][nj][half*2 + 1] * sscale[col + 1] + sshift[col + 1];
                if (RELU) { v0 = fmaxf(v0, 0.f); v1 = fmaxf(v1, 0.f); }
                v0 += res.x; v1 += res.y;
                *(float2*)(orow + col) = make_float2(v0, v1);
                if (COMPT) {
                    sW[row*WPITCH + col]     = v0;
                    sW[row*WPITCH + col + 1] = v1;
                }
            }
        }

    if (COMPT) {
        __syncthreads();
        // T = h_final(sW, 128x128) @ W2(sW2, 128x16); warp w owns rows [w*16, w*16+16)
        float dt[2][4] = {};
        #pragma unroll
        for (int ks = 0; ks < 16; ks++) {
            const int kk = ks * 8;
            uint32_t a[4];
            const float* ap = sW + (warp*16 + gid)*WPITCH + kk + tig;
            a[0] = __float_as_uint(ap[0]);
            a[1] = __float_as_uint(ap[8*WPITCH]);
            a[2] = __float_as_uint(ap[4]);
            a[3] = __float_as_uint(ap[8*WPITCH + 4]);
            #pragma unroll
            for (int nt = 0; nt < 2; nt++) {
                uint32_t b0 = __float_as_uint(sW2[(kk + tig)*TPITCH     + nt*8 + gid]);
                uint32_t b1 = __float_as_uint(sW2[(kk + tig + 4)*TPITCH + nt*8 + gid]);
                mma_tf32(dt[nt], a, b0, b1);
            }
        }
        #pragma unroll
        for (int nt = 0; nt < 2; nt++)
            #pragma unroll
            for (int half = 0; half < 2; half++) {
                const int row = warp*16 + gid + half*8;
                const int col = nt*8 + tig*2;
                float* trow = g_t + (size_t)(row0 + row) * 14;
                if (col < 14)     trow[col]     = dt[nt][half*2 + 0];
                if (col + 1 < 14) trow[col + 1] = dt[nt][half*2 + 1];
            }
    }
}

// ================= K4: per-graph logits-agg + softmax + pooling + losses + pm =================
__global__ void k_pool(const int* __restrict__ ei, const float* __restrict__ abl) {
    __shared__ float sh[NPG * H];
    __shared__ float t1[NPG*NCL], t2[NPG*NCL], ssl[NPG*NCL], sd[NPG*NCL];
    __shared__ float adj[NPG * NPG];
    __shared__ int   se[EPG], de[EPG], degi[NPG];
    __shared__ float red[128], red2[128];
    const int g = blockIdx.x, tid = threadIdx.x;  // 128
    const float* hg = g_h + (size_t)g * NPG * H;
    for (int i = tid; i < NPG * H; i += 128) sh[i] = hg[i];
    for (int i = tid; i < NPG * 14; i += 128) {
        int n = i / 14, c = i - n*14;
        float v = g_t[(size_t)g*NPG*14 + i];
        if (c < 7) t1[n*7 + c] = v; else t2[n*7 + (c-7)] = v;
    }
    for (int i = tid; i < NPG * NPG; i += 128) adj[i] = 0.f;
    for (int i = tid; i < NPG * NCL; i += 128) ssl[i] = 0.f;
    if (tid < NPG) degi[tid] = 0;
    if (tid < EPG) {
        se[tid] = ei[(size_t)g*EPG + tid]                 - g*NPG;
        de[tid] = ei[(size_t)NEDGE + (size_t)g*EPG + tid] - g*NPG;
    }
    __syncthreads();
    if (tid < EPG) {
        atomicAdd(&degi[de[tid]], 1);
        atomicAdd(&adj[se[tid]*NPG + de[tid]], 1.f);
        #pragma unroll
        for (int c = 0; c < NCL; c++)
            atomicAdd(&ssl[de[tid]*NCL + c], t1[se[tid]*NCL + c]);
    }
    __syncthreads();
    for (int i = tid; i < NPG * NCL; i += 128) {
        int n = i / NCL;
        ssl[i] = ssl[i] / fmaxf((float)degi[n], 1.f) + t2[i] + abl[i - n*NCL];
    }
    __syncthreads();
    float ent_local = 0.f;
    if (tid < NPG) {
        float v[NCL], mx = -1e30f;
        #pragma unroll
        for (int c = 0; c < NCL; c++) { v[c] = ssl[tid*NCL + c]; mx = fmaxf(mx, v[c]); }
        float s = 0.f;
        #pragma unroll
        for (int c = 0; c < NCL; c++) { v[c] = expf(v[c] - mx); s += v[c]; }
        float inv = 1.f / s;
        #pragma unroll
        for (int c = 0; c < NCL; c++) {
            float p = v[c] * inv;
            sd[tid*NCL + c] = p;
            ent_local += -p * logf(p + 1e-15f);
        }
    }
    __syncthreads();
    float* x2g = g_x2 + (size_t)g * NCL * H;
    float pmsum = 0.f;
    #pragma unroll
    for (int c = 0; c < NCL; c++) {
        float a = 0.f;
        #pragma unroll
        for (int n = 0; n < NPG; n++) a += sd[n*NCL + c] * sh[n*128 + tid];
        x2g[c*128 + tid] = a;
        pmsum += a;
    }
    g_pm[(size_t)g*128 + tid] = pmsum * (1.f / 7.f);   // fused first pmean
    float link_local = 0.f;
    for (int p = tid; p < NPG * NPG; p += 128) {
        int n = p / NPG, m = p - NPG*n;
        float ss = 0.f;
        #pragma unroll
        for (int c = 0; c < NCL; c++) ss += sd[n*NCL + c] * sd[m*NCL + c];
        float dd = adj[p] - ss;
        link_local += dd * dd;
    }
    red[tid] = link_local; red2[tid] = ent_local;
    __syncthreads();
    for (int s = 64; s > 0; s >>= 1) {
        if (tid < s) { red[tid] += red[tid + s]; red2[tid] += red2[tid + s]; }
        __syncthreads();
    }
    if (tid == 0) { g_linkpart[g] = red[0]; g_entpart[g] = red2[0]; }
}

// ================= K5: per-graph mean of clusters (for li=3) =================
__global__ void k_pmean() {
    int idx = blockIdx.x * 256 + threadIdx.x;
    int g = idx >> 7, col = idx & 127;
    const float* xg = g_x2 + (size_t)g * NCL * H + col;
    float a = 0.f;
    #pragma unroll
    for (int c = 0; c < NCL; c++) a += xg[c * 128];
    g_pm[idx] = a * (1.f / 7.f);
}

// ================= K6: readout =================
__global__ void k_readout(const float* __restrict__ linW, const float* __restrict__ linb,
                          float* __restrict__ out) {
    const int g = blockIdx.x, tid = threadIdx.x;  // 128
    const float* xg = g_x2 + (size_t)g * NCL * H;
    float v = 0.f;
    #pragma unroll
    for (int c = 0; c < NCL; c++) v += xg[c * 128 + tid];
    v *= (1.f / 7.f);
    __shared__ float red[128];
    red[tid] = v * linW[tid];
    __syncthreads();
    for (int s = 64; s > 0; s >>= 1) {
        if (tid < s) red[tid] += red[tid + s];
        __syncthreads();
    }
    if (tid == 0) out[g] = 1.f / (1.f + expf(-(red[0] + linb[0])));
}

// ================= K7: deterministic loss reduction =================
__global__ void k_reduce(float* __restrict__ out) {
    __shared__ float s1[1024], s2[1024];
    const int tid = threadIdx.x;
    float a = 0.f, b = 0.f;
    for (int i = tid; i < NB; i += 1024) { a += g_linkpart[i]; b += g_entpart[i]; }
    s1[tid] = a; s2[tid] = b;
    __syncthreads();
    for (int s = 512; s > 0; s >>= 1) {
        if (tid < s) { s1[tid] += s1[tid + s]; s2[tid] += s2[tid + s]; }
        __syncthreads();
    }
    if (tid == 0) {
        out[NB]     = sqrtf(s1[0]) / 11075584.f;   // nb * 26 * 26
        out[NB + 1] = s2[0] / (float)NTOT;
    }
}

extern "C" void kernel_launch(void* const* d_in, const int* in_sizes, int n_in,
                              void* d_out, int out_size) {
    (void)in_sizes; (void)n_in; (void)out_size;
    const int*   x    = (const int*)  d_in[0];
    const int*   ei   = (const int*)  d_in[1];
    const float* emb  = (const float*)d_in[3];
    const float* cWl  = (const float*)d_in[4];
    const float* cbl  = (const float*)d_in[5];
    const float* cWr  = (const float*)d_in[6];
    const float* bng  = (const float*)d_in[7];
    const float* bnb  = (const float*)d_in[8];
    const float* bnm  = (const float*)d_in[9];
    const float* bnv  = (const float*)d_in[10];
    const float* aWl  = (const float*)d_in[11];
    const float* abl  = (const float*)d_in[12];
    const float* aWr  = (const float*)d_in[13];
    const float* linW = (const float*)d_in[14];
    const float* linb = (const float*)d_in[15];
    float* out = (float*)d_out;

    const int gemm_smem = (128*WPITCH + 128*APITCH) * 4;     // 102400
    cudaFuncSetAttribute(k_gemm_tc<1,0,0>, cudaFuncAttributeMaxDynamicSharedMemorySize, gemm_smem);
    cudaFuncSetAttribute(k_gemm_tc<1,0,1>, cudaFuncAttributeMaxDynamicSharedMemorySize, gemm_smem);
    cudaFuncSetAttribute(k_gemm_tc<0,1,0>, cudaFuncAttributeMaxDynamicSharedMemorySize, gemm_smem);

    k_encode<<<NTOT / 32, 128>>>(x, emb);

    // layer 0
    k_agg2<<<NB, 128>>>(ei);
    k_gemm_tc<1,0,0><<<NTOT / 128, 256, gemm_smem>>>(
        cWl, cWr, cbl, bng, bnb, bnm, bnv, nullptr, nullptr);
    // layer 1 (+ fused T = h@[aWl|aWr])
    k_agg2<<<NB, 128>>>(ei);
    k_gemm_tc<1,0,1><<<NTOT / 128, 256, gemm_smem>>>(
        cWl + 16384, cWr + 16384, cbl + 128,
        bng + 128, bnb + 128, bnm + 128, bnv + 128, aWl, aWr);

    k_pool<<<NB, 128>>>(ei, abl);     // also writes g_pm (first pmean fused)

    // pooled layer 2
    k_gemm_tc<0,1,0><<<NB * NCL / 128, 256, gemm_smem>>>(
        cWl + 2*16384, cWr + 2*16384, cbl + 2*128,
        bng + 2*128, bnb + 2*128, bnm + 2*128, bnv + 2*128, nullptr, nullptr);
    // pooled layer 3
    k_pmean<<<NB * 128 / 256, 256>>>();
    k_gemm_tc<0,1,0><<<NB * NCL / 128, 256, gemm_smem>>>(
        cWl + 3*16384, cWr + 3*16384, cbl + 3*128,
        bng + 3*128, bnb + 3*128, bnm + 3*128, bnv + 3*128, nullptr, nullptr);

    k_readout<<<NB, 128>>>(linW, linb, out);
    k_reduce<<<1, 1024>>>(out);
}

// round 9
// speedup vs baseline: 1.4822x; 1.0484x over previous
#include <cuda_runtime.h>
#include <math.h>
#include <stdint.h>

#define H     128
#define NB    16384
#define NPG   26
#define EPG   52
#define NCL   7
#define NTOT  (NB*NPG)      // 425984
#define NEDGE (NB*EPG)      // 851968

// ------------- scratch: device globals (no runtime allocation) -------------
__device__ float g_h[NTOT*H];        // node features (in-place per layer)
__device__ float g_mean[NTOT*H];     // neighbor means
__device__ float g_t[NTOT*14];       // [n*14+c]: c<7 -> h@aWl, c>=7 -> h@aWr
__device__ float g_x2[NB*NCL*H];     // pooled cluster features (in-place)
__device__ float g_pm[NB*H];         // per-graph mean of clusters
__device__ float g_linkpart[NB];
__device__ float g_entpart[NB];

// ---- cp.async helpers ----
#define CP_ASYNC16(dst, src) \
    asm volatile("cp.async.cg.shared.global [%0], [%1], 16;\n" :: "r"(dst), "l"(src))
#define CP_COMMIT() asm volatile("cp.async.commit_group;\n" ::: "memory")
#define CP_WAIT(n)  asm volatile("cp.async.wait_group %0;\n" :: "n"(n) : "memory")

// ================= K1: atom encoder (R2/R4-proven) =================
__global__ void k_encode(const int* __restrict__ x, const float* __restrict__ emb) {
    const int tid = threadIdx.x;
    const int n0  = blockIdx.x * 32;
    __shared__ int sx[32 * 9];
    for (int i = tid; i < 32 * 9; i += 128) sx[i] = x[(size_t)n0 * 9 + i];
    __syncthreads();
    for (int nn = 0; nn < 32; nn++) {
        float acc = 0.f;
        #pragma unroll
        for (int f = 0; f < 9; f++) {
            int v = sx[nn * 9 + f];
            acc += emb[((size_t)f * 119 + v) * 128 + tid];
        }
        g_h[(size_t)(n0 + nn) * 128 + tid] = acc;
    }
}

// ================= K2: neighbor-mean via CSR counting sort (2 graphs/block) =================
__global__ __launch_bounds__(256)
void k_agg2b(const int* __restrict__ ei) {
    __shared__ float sh[2 * NPG * H];
    __shared__ int   se[104], sde[104], sdeg[52], sstart[2][27], soffs[52], ssrt[104];
    __shared__ float srdeg[52];
    const int g0 = blockIdx.x * 2, tid = threadIdx.x;
    const float* hg = g_h + (size_t)g0 * NPG * H;
    for (int i = tid; i < 2 * NPG * 32; i += 256)
        *(float4*)&sh[i*4] = *(const float4*)(hg + (size_t)i*4);
    if (tid < 52) sdeg[tid] = 0;
    __syncthreads();
    if (tid < 104) {
        int q = tid / 52, e = tid - q*52, g = g0 + q;
        int s = ei[(size_t)g*EPG + e]                 - g*NPG;
        int d = ei[(size_t)NEDGE + (size_t)g*EPG + e] - g*NPG;
        se[tid] = s; sde[tid] = d;
        atomicAdd(&sdeg[q*26 + d], 1);
    }
    __syncthreads();
    if (tid < 2) {
        int acc = 0;
        #pragma unroll
        for (int n = 0; n < 26; n++) { sstart[tid][n] = acc; acc += sdeg[tid*26 + n]; }
        sstart[tid][26] = acc;
    }
    if (tid < 52) srdeg[tid] = 1.f / fmaxf((float)sdeg[tid], 1.f);
    __syncthreads();
    if (tid < 52) soffs[tid] = sstart[tid/26][tid%26];
    __syncthreads();
    if (tid < 104) {
        int q = tid / 52;
        int pos = atomicAdd(&soffs[q*26 + sde[tid]], 1);
        ssrt[q*52 + pos] = se[tid];
    }
    __syncthreads();
    const int q = tid >> 7, c = tid & 127;
    const int* srt = ssrt + q*52;
    float* mg = g_mean + ((size_t)g0 + q) * NPG * H;
    #pragma unroll 2
    for (int n = 0; n < 26; n++) {
        float acc = 0.f;
        int b = sstart[q][n], e2 = sstart[q][n+1];
        for (int j = b; j < e2; j++) acc += sh[(q*26 + srt[j])*H + c];
        mg[(size_t)n*H + c] = acc * srdeg[q*26 + n];
    }
}

// ================= tf32 mma.sync helper (verified layout) =================
__device__ __forceinline__ void mma_tf32(float* d, const uint32_t* a,
                                         uint32_t b0, uint32_t b1) {
    asm volatile(
        "mma.sync.aligned.m16n8k8.row.col.f32.tf32.tf32.f32 "
        "{%0,%1,%2,%3}, {%4,%5,%6,%7}, {%8,%9}, {%0,%1,%2,%3};\n"
        : "+f"(d[0]), "+f"(d[1]), "+f"(d[2]), "+f"(d[3])
        : "r"(a[0]), "r"(a[1]), "r"(a[2]), "r"(a[3]), "r"(b0), "r"(b1));
}

#define WPITCH 132
#define APITCH 68
#define TPITCH 17
#define WP2    132   // pipelined W chunk pitch
#define AP2    36    // pipelined A chunk pitch

// ================= K3a: pipelined tensor-core GEMM (cp.async double-buffered) =================
// Out = bn([mean||h] @ [Wl;Wr] + bl)(+relu) + residual, in place.
template<int RELU, int POOLED>
__global__ __launch_bounds__(256, 2)
void k_gemm_pipe(const float* __restrict__ Wl, const float* __restrict__ Wr,
                 const float* __restrict__ bl,
                 const float* __restrict__ bng, const float* __restrict__ bnb,
                 const float* __restrict__ bnm, const float* __restrict__ bnv)
{
    extern __shared__ float smem[];
    float* sWb0 = smem;                         // 32 x WP2
    float* sWb1 = smem + 32*WP2;                // 32 x WP2
    float* sAb0 = smem + 2*32*WP2;              // 128 x AP2
    float* sAb1 = smem + 2*32*WP2 + 128*AP2;    // 128 x AP2
    __shared__ float sscale[128], sshift[128];

    const int tid  = threadIdx.x;
    const int row0 = blockIdx.x * 128;
    const float* Am = POOLED ? g_pm : g_mean;
    float*       Ah = POOLED ? g_x2 : g_h;

    if (tid < 128) {
        float sc = bng[tid] * rsqrtf(bnv[tid] + 1e-5f);
        sscale[tid] = sc;
        sshift[tid] = bnb[tid] + sc * (bl[tid] - bnm[tid]);
    }

    const int lane = tid & 31, warp = tid >> 5;
    const int gid = lane >> 2, tig = lane & 3;
    const int wr0 = (warp & 3) * 32;
    const int wc0 = (warp >> 2) * 64;
    float d[2][8][4] = {};

    // issue chunk ch into buffer buf (A: 128x32, W: 32x128)
    auto issue = [&](int ch, float* sA, float* sW) {
        #pragma unroll
        for (int v = 0; v < 4; v++) {
            int i  = tid + v*256;              // 0..1023
            int r  = i >> 3, c4 = (i & 7) * 4;
            int gk = ch*32 + c4;
            int grow = row0 + r;
            const float* ap;
            if (gk < 128) {
                int mrow = POOLED ? (grow / 7) : grow;
                ap = Am + (size_t)mrow*128 + gk;
            } else {
                ap = Ah + (size_t)grow*128 + (gk - 128);
            }
            uint32_t dst = (uint32_t)__cvta_generic_to_shared(&sA[r*AP2 + c4]);
            CP_ASYNC16(dst, ap);
        }
        #pragma unroll
        for (int v = 0; v < 4; v++) {
            int i  = tid + v*256;
            int r  = i >> 5, c4 = (i & 31) * 4;
            int gk = ch*32 + r;
            const float* wp = (gk < 128) ? (Wl + (size_t)gk*128 + c4)
                                         : (Wr + (size_t)(gk - 128)*128 + c4);
            uint32_t dst = (uint32_t)__cvta_generic_to_shared(&sW[r*WP2 + c4]);
            CP_ASYNC16(dst, wp);
        }
        CP_COMMIT();
    };

    issue(0, sAb0, sWb0);
    #pragma unroll
    for (int ch = 0; ch < 8; ch++) {
        if (ch < 7) issue(ch + 1, ((ch+1) & 1) ? sAb1 : sAb0,
                                   ((ch+1) & 1) ? sWb1 : sWb0);
        if (ch < 7) { CP_WAIT(1); } else { CP_WAIT(0); }
        __syncthreads();
        const float* sA = (ch & 1) ? sAb1 : sAb0;
        const float* sW = (ch & 1) ? sWb1 : sWb0;
        #pragma unroll
        for (int ks = 0; ks < 4; ks++) {
            const int kk = ks * 8;
            uint32_t a[2][4];
            #pragma unroll
            for (int mi = 0; mi < 2; mi++) {
                const float* ap = sA + (wr0 + mi*16 + gid)*AP2 + kk + tig;
                a[mi][0] = __float_as_uint(ap[0]);
                a[mi][1] = __float_as_uint(ap[8*AP2]);
                a[mi][2] = __float_as_uint(ap[4]);
                a[mi][3] = __float_as_uint(ap[8*AP2 + 4]);
            }
            const float* bp = sW + (kk + tig)*WP2 + wc0 + gid;
            #pragma unroll
            for (int nj = 0; nj < 8; nj++) {
                uint32_t b0 = __float_as_uint(bp[nj*8]);
                uint32_t b1 = __float_as_uint(bp[nj*8 + 4*WP2]);
                mma_tf32(d[0][nj], a[0], b0, b1);
                mma_tf32(d[1][nj], a[1], b0, b1);
            }
        }
        __syncthreads();
    }

    // epilogue: bn + (relu) + residual (re-read from global), in-place write
    #pragma unroll
    for (int mi = 0; mi < 2; mi++)
        #pragma unroll
        for (int half = 0; half < 2; half++) {
            const int row = wr0 + mi*16 + gid + half*8;
            float* orow = Ah + (size_t)(row0 + row) * 128;
            #pragma unroll
            for (int nj = 0; nj < 8; nj++) {
                const int col = wc0 + nj*8 + tig*2;
                float2 res = *(float2*)(orow + col);
                float v0 = d[mi][nj][half*2 + 0] * sscale[col]     + sshift[col];
                float v1 = d[mi][nj][half*2 + 1] * sscale[col + 1] + sshift[col + 1];
                if (RELU) { v0 = fmaxf(v0, 0.f); v1 = fmaxf(v1, 0.f); }
                *(float2*)(orow + col) = make_float2(v0 + res.x, v1 + res.y);
            }
        }
}

// ================= K3b: R8-proven GEMM with fused T epilogue (li=1 only) =================
__global__ __launch_bounds__(256, 2)
void k_gemm_tcT(const float* __restrict__ Wl, const float* __restrict__ Wr,
                const float* __restrict__ bl,
                const float* __restrict__ bng, const float* __restrict__ bnb,
                const float* __restrict__ bnm, const float* __restrict__ bnv,
                const float* __restrict__ aWl, const float* __restrict__ aWr)
{
    extern __shared__ float smem[];
    float* sW = smem;                  // 128 x WPITCH (weights; later h_final)
    float* sA = smem + 128*WPITCH;     // 128 x APITCH (64-wide k chunk)
    __shared__ float sscale[128], sshift[128];
    __shared__ float sW2[128*TPITCH];

    const int tid  = threadIdx.x;
    const int row0 = blockIdx.x * 128;

    if (tid < 128) {
        float sc = bng[tid] * rsqrtf(bnv[tid] + 1e-5f);
        sscale[tid] = sc;
        sshift[tid] = bnb[tid] + sc * (bl[tid] - bnm[tid]);
    }
    for (int i = tid; i < 128*16; i += 256) {
        int k = i >> 4, c = i & 15;
        float v = 0.f;
        if (c < 7)       v = aWl[k*NCL + c];
        else if (c < 14) v = aWr[k*NCL + (c - 7)];
        sW2[k*TPITCH + c] = v;
    }

    const int lane = tid & 31, warp = tid >> 5;
    const int gid = lane >> 2, tig = lane & 3;
    const int wr0 = (warp & 3) * 32;
    const int wc0 = (warp >> 2) * 64;
    float d[2][8][4] = {};

    #pragma unroll
    for (int phase = 0; phase < 2; phase++) {
        const float* Wop = phase == 0 ? Wl : Wr;
        __syncthreads();
        for (int i = tid; i < 128*32; i += 256) {
            int r = i >> 5, c = (i & 31) * 4;
            *(float4*)&sW[r*WPITCH + c] = *(const float4*)(Wop + (size_t)r*128 + c);
        }
        #pragma unroll
        for (int kc = 0; kc < 2; kc++) {
            __syncthreads();
            for (int i = tid; i < 128*16; i += 256) {
                int r = i >> 4, c = (i & 15) * 4;
                int grow = row0 + r;
                const float* ap = (phase == 0) ? (g_mean + (size_t)grow*128)
                                               : (g_h    + (size_t)grow*128);
                *(float4*)&sA[r*APITCH + c] = *(const float4*)(ap + kc*64 + c);
            }
            __syncthreads();
            #pragma unroll
            for (int ks = 0; ks < 8; ks++) {
                const int kk = ks * 8;
                uint32_t a[2][4];
                #pragma unroll
                for (int mi = 0; mi < 2; mi++) {
                    const float* ap = sA + (wr0 + mi*16 + gid)*APITCH + kk + tig;
                    a[mi][0] = __float_as_uint(ap[0]);
                    a[mi][1] = __float_as_uint(ap[8*APITCH]);
                    a[mi][2] = __float_as_uint(ap[4]);
                    a[mi][3] = __float_as_uint(ap[8*APITCH + 4]);
                }
                const float* bp = sW + (kc*64 + kk + tig)*WPITCH + wc0 + gid;
                #pragma unroll
                for (int nj = 0; nj < 8; nj++) {
                    uint32_t b0 = __float_as_uint(bp[nj*8]);
                    uint32_t b1 = __float_as_uint(bp[nj*8 + 4*WPITCH]);
                    mma_tf32(d[0][nj], a[0], b0, b1);
                    mma_tf32(d[1][nj], a[1], b0, b1);
                }
            }
        }
    }

    __syncthreads();   // all warps done reading sW before overwrite

    #pragma unroll
    for (int mi = 0; mi < 2; mi++)
        #pragma unroll
        for (int half = 0; half < 2; half++) {
            const int row = wr0 + mi*16 + gid + half*8;
            float* orow = g_h + (size_t)(row0 + row) * 128;
            #pragma unroll
            for (int nj = 0; nj < 8; nj++) {
                const int col = wc0 + nj*8 + tig*2;
                float2 res = *(float2*)(orow + col);
                float v0 = d[mi][nj][half*2 + 0] * sscale[col]     + sshift[col];
                float v1 = d[mi][nj][half*2 + 1] * sscale[col + 1] + sshift[col + 1];
                v0 = fmaxf(v0, 0.f); v1 = fmaxf(v1, 0.f);
                v0 += res.x; v1 += res.y;
                *(float2*)(orow + col) = make_float2(v0, v1);
                sW[row*WPITCH + col]     = v0;
                sW[row*WPITCH + col + 1] = v1;
            }
        }

    __syncthreads();
    // T = h_final(sW, 128x128) @ W2(sW2, 128x16); warp w owns rows [w*16, w*16+16)
    float dt[2][4] = {};
    #pragma unroll
    for (int ks = 0; ks < 16; ks++) {
        const int kk = ks * 8;
        uint32_t a[4];
        const float* ap = sW + (warp*16 + gid)*WPITCH + kk + tig;
        a[0] = __float_as_uint(ap[0]);
        a[1] = __float_as_uint(ap[8*WPITCH]);
        a[2] = __float_as_uint(ap[4]);
        a[3] = __float_as_uint(ap[8*WPITCH + 4]);
        #pragma unroll
        for (int nt = 0; nt < 2; nt++) {
            uint32_t b0 = __float_as_uint(sW2[(kk + tig)*TPITCH     + nt*8 + gid]);
            uint32_t b1 = __float_as_uint(sW2[(kk + tig + 4)*TPITCH + nt*8 + gid]);
            mma_tf32(dt[nt], a, b0, b1);
        }
    }
    #pragma unroll
    for (int nt = 0; nt < 2; nt++)
        #pragma unroll
        for (int half = 0; half < 2; half++) {
            const int row = warp*16 + gid + half*8;
            const int col = nt*8 + tig*2;
            float* trow = g_t + (size_t)(row0 + row) * 14;
            if (col < 14)     trow[col]     = dt[nt][half*2 + 0];
            if (col + 1 < 14) trow[col + 1] = dt[nt][half*2 + 1];
        }
}

// ================= K4: per-graph logits-agg + softmax + pooling + losses + pm =================
__global__ void k_pool(const int* __restrict__ ei, const float* __restrict__ abl) {
    __shared__ float sh[NPG * H];
    __shared__ float t1[NPG*NCL], t2[NPG*NCL], ssl[NPG*NCL], sd[NPG*NCL];
    __shared__ float adj[NPG * NPG];
    __shared__ int   se[EPG], de[EPG], degi[NPG];
    __shared__ float red[128], red2[128];
    const int g = blockIdx.x, tid = threadIdx.x;  // 128
    const float* hg = g_h + (size_t)g * NPG * H;
    for (int i = tid; i < NPG * H; i += 128) sh[i] = hg[i];
    for (int i = tid; i < NPG * 14; i += 128) {
        int n = i / 14, c = i - n*14;
        float v = g_t[(size_t)g*NPG*14 + i];
        if (c < 7) t1[n*7 + c] = v; else t2[n*7 + (c-7)] = v;
    }
    for (int i = tid; i < NPG * NPG; i += 128) adj[i] = 0.f;
    for (int i = tid; i < NPG * NCL; i += 128) ssl[i] = 0.f;
    if (tid < NPG) degi[tid] = 0;
    if (tid < EPG) {
        se[tid] = ei[(size_t)g*EPG + tid]                 - g*NPG;
        de[tid] = ei[(size_t)NEDGE + (size_t)g*EPG + tid] - g*NPG;
    }
    __syncthreads();
    if (tid < EPG) {
        atomicAdd(&degi[de[tid]], 1);
        atomicAdd(&adj[se[tid]*NPG + de[tid]], 1.f);
        #pragma unroll
        for (int c = 0; c < NCL; c++)
            atomicAdd(&ssl[de[tid]*NCL + c], t1[se[tid]*NCL + c]);
    }
    __syncthreads();
    for (int i = tid; i < NPG * NCL; i += 128) {
        int n = i / NCL;
        ssl[i] = ssl[i] / fmaxf((float)degi[n], 1.f) + t2[i] + abl[i - n*NCL];
    }
    __syncthreads();
    float ent_local = 0.f;
    if (tid < NPG) {
        float v[NCL], mx = -1e30f;
        #pragma unroll
        for (int c = 0; c < NCL; c++) { v[c] = ssl[tid*NCL + c]; mx = fmaxf(mx, v[c]); }
        float s = 0.f;
        #pragma unroll
        for (int c = 0; c < NCL; c++) { v[c] = expf(v[c] - mx); s += v[c]; }
        float inv = 1.f / s;
        #pragma unroll
        for (int c = 0; c < NCL; c++) {
            float p = v[c] * inv;
            sd[tid*NCL + c] = p;
            ent_local += -p * logf(p + 1e-15f);
        }
    }
    __syncthreads();
    float* x2g = g_x2 + (size_t)g * NCL * H;
    float pmsum = 0.f;
    #pragma unroll
    for (int c = 0; c < NCL; c++) {
        float a = 0.f;
        #pragma unroll
        for (int n = 0; n < NPG; n++) a += sd[n*NCL + c] * sh[n*128 + tid];
        x2g[c*128 + tid] = a;
        pmsum += a;
    }
    g_pm[(size_t)g*128 + tid] = pmsum * (1.f / 7.f);
    float link_local = 0.f;
    for (int p = tid; p < NPG * NPG; p += 128) {
        int n = p / NPG, m = p - NPG*n;
        float ss = 0.f;
        #pragma unroll
        for (int c = 0; c < NCL; c++) ss += sd[n*NCL + c] * sd[m*NCL + c];
        float dd = adj[p] - ss;
        link_local += dd * dd;
    }
    red[tid] = link_local; red2[tid] = ent_local;
    __syncthreads();
    for (int s = 64; s > 0; s >>= 1) {
        if (tid < s) { red[tid] += red[tid + s]; red2[tid] += red2[tid + s]; }
        __syncthreads();
    }
    if (tid == 0) { g_linkpart[g] = red[0]; g_entpart[g] = red2[0]; }
}

// ================= K5: per-graph mean of clusters (for li=3) =================
__global__ void k_pmean() {
    int idx = blockIdx.x * 256 + threadIdx.x;
    int g = idx >> 7, col = idx & 127;
    const float* xg = g_x2 + (size_t)g * NCL * H + col;
    float a = 0.f;
    #pragma unroll
    for (int c = 0; c < NCL; c++) a += xg[c * 128];
    g_pm[idx] = a * (1.f / 7.f);
}

// ================= K6: readout =================
__global__ void k_readout(const float* __restrict__ linW, const float* __restrict__ linb,
                          float* __restrict__ out) {
    const int g = blockIdx.x, tid = threadIdx.x;  // 128
    const float* xg = g_x2 + (size_t)g * NCL * H;
    float v = 0.f;
    #pragma unroll
    for (int c = 0; c < NCL; c++) v += xg[c * 128 + tid];
    v *= (1.f / 7.f);
    __shared__ float red[128];
    red[tid] = v * linW[tid];
    __syncthreads();
    for (int s = 64; s > 0; s >>= 1) {
        if (tid < s) red[tid] += red[tid + s];
        __syncthreads();
    }
    if (tid == 0) out[g] = 1.f / (1.f + expf(-(red[0] + linb[0])));
}

// ================= K7: deterministic loss reduction =================
__global__ void k_reduce(float* __restrict__ out) {
    __shared__ float s1[1024], s2[1024];
    const int tid = threadIdx.x;
    float a = 0.f, b = 0.f;
    for (int i = tid; i < NB; i += 1024) { a += g_linkpart[i]; b += g_entpart[i]; }
    s1[tid] = a; s2[tid] = b;
    __syncthreads();
    for (int s = 512; s > 0; s >>= 1) {
        if (tid < s) { s1[tid] += s1[tid + s]; s2[tid] += s2[tid + s]; }
        __syncthreads();
    }
    if (tid == 0) {
        out[NB]     = sqrtf(s1[0]) / 11075584.f;   // nb * 26 * 26
        out[NB + 1] = s2[0] / (float)NTOT;
    }
}

extern "C" void kernel_launch(void* const* d_in, const int* in_sizes, int n_in,
                              void* d_out, int out_size) {
    (void)in_sizes; (void)n_in; (void)out_size;
    const int*   x    = (const int*)  d_in[0];
    const int*   ei   = (const int*)  d_in[1];
    const float* emb  = (const float*)d_in[3];
    const float* cWl  = (const float*)d_in[4];
    const float* cbl  = (const float*)d_in[5];
    const float* cWr  = (const float*)d_in[6];
    const float* bng  = (const float*)d_in[7];
    const float* bnb  = (const float*)d_in[8];
    const float* bnm  = (const float*)d_in[9];
    const float* bnv  = (const float*)d_in[10];
    const float* aWl  = (const float*)d_in[11];
    const float* abl  = (const float*)d_in[12];
    const float* aWr  = (const float*)d_in[13];
    const float* linW = (const float*)d_in[14];
    const float* linb = (const float*)d_in[15];
    float* out = (float*)d_out;

    const int pipe_smem = (2*32*WP2 + 2*128*AP2) * 4;        // 70656
    const int tcT_smem  = (128*WPITCH + 128*APITCH) * 4;     // 102400
    cudaFuncSetAttribute(k_gemm_pipe<1,0>, cudaFuncAttributeMaxDynamicSharedMemorySize, pipe_smem);
    cudaFuncSetAttribute(k_gemm_pipe<0,1>, cudaFuncAttributeMaxDynamicSharedMemorySize, pipe_smem);
    cudaFuncSetAttribute(k_gemm_tcT, cudaFuncAttributeMaxDynamicSharedMemorySize, tcT_smem);

    k_encode<<<NTOT / 32, 128>>>(x, emb);

    // layer 0
    k_agg2b<<<NB / 2, 256>>>(ei);
    k_gemm_pipe<1,0><<<NTOT / 128, 256, pipe_smem>>>(
        cWl, cWr, cbl, bng, bnb, bnm, bnv);
    // layer 1 (+ fused T = h@[aWl|aWr])
    k_agg2b<<<NB / 2, 256>>>(ei);
    k_gemm_tcT<<<NTOT / 128, 256, tcT_smem>>>(
        cWl + 16384, cWr + 16384, cbl + 128,
        bng + 128, bnb + 128, bnm + 128, bnv + 128, aWl, aWr);

    k_pool<<<NB, 128>>>(ei, abl);     // also writes g_pm (first pmean fused)

    // pooled layer 2
    k_gemm_pipe<0,1><<<NB * NCL / 128, 256, pipe_smem>>>(
        cWl + 2*16384, cWr + 2*16384, cbl + 2*128,
        bng + 2*128, bnb + 2*128, bnm + 2*128, bnv + 2*128);
    // pooled layer 3
    k_pmean<<<NB * 128 / 256, 256>>>();
    k_gemm_pipe<0,1><<<NB * NCL / 128, 256, pipe_smem>>>(
        cWl + 3*16384, cWr + 3*16384, cbl + 3*128,
        bng + 3*128, bnb + 3*128, bnm + 3*128, bnv + 3*128);

    k_readout<<<NB, 128>>>(linW, linb, out);
    k_reduce<<<1, 1024>>>(out);
}

// round 10
// speedup vs baseline: 1.6079x; 1.0848x over previous
#include <cuda_runtime.h>
#include <math.h>
#include <stdint.h>

#define H     128
#define NB    16384
#define NPG   26
#define EPG   52
#define NCL   7
#define NTOT  (NB*NPG)      // 425984
#define NEDGE (NB*EPG)      // 851968

// ------------- scratch: device globals (no runtime allocation) -------------
__device__ float g_h[NTOT*H];        // node features (in-place per layer)
__device__ float g_mean[NTOT*H];     // neighbor means
__device__ float g_t[NTOT*14];       // [n*14+c]: c<7 -> h@aWl, c>=7 -> h@aWr
__device__ float g_x2[NB*NCL*H];     // pooled cluster features (in-place)
__device__ float g_pm[NB*H];         // per-graph mean of clusters
__device__ float g_linkpart[NB];
__device__ float g_entpart[NB];

// ---- cp.async helpers ----
#define CP_ASYNC16(dst, src) \
    asm volatile("cp.async.cg.shared.global [%0], [%1], 16;\n" :: "r"(dst), "l"(src))
#define CP_COMMIT() asm volatile("cp.async.commit_group;\n" ::: "memory")
#define CP_WAIT(n)  asm volatile("cp.async.wait_group %0;\n" :: "n"(n) : "memory")

// ================= K1: fused atom encoder + layer-0 neighbor mean =================
// 1 graph/block, 128 threads (thread = feature column).
__global__ __launch_bounds__(128)
void k_encagg(const int* __restrict__ x, const float* __restrict__ emb,
              const int* __restrict__ ei) {
    __shared__ float sh[NPG * H];
    __shared__ int   sx[NPG * 9];
    __shared__ int   se[EPG], sde[EPG], sdeg[NPG], sstart[NPG+1], soffs[NPG], ssrt[EPG];
    __shared__ float srdeg[NPG];
    const int g = blockIdx.x, tid = threadIdx.x;
    for (int i = tid; i < NPG*9; i += 128) sx[i] = x[(size_t)g*NPG*9 + i];
    if (tid < NPG) sdeg[tid] = 0;
    if (tid < EPG) {
        se[tid]  = ei[(size_t)g*EPG + tid]                 - g*NPG;
        sde[tid] = ei[(size_t)NEDGE + (size_t)g*EPG + tid] - g*NPG;
    }
    __syncthreads();
    if (tid < EPG) atomicAdd(&sdeg[sde[tid]], 1);
    __syncthreads();
    if (tid == 0) {
        int acc = 0;
        #pragma unroll
        for (int n = 0; n < NPG; n++) { sstart[n] = acc; acc += sdeg[n]; }
        sstart[NPG] = acc;
    }
    if (tid < NPG) srdeg[tid] = 1.f / fmaxf((float)sdeg[tid], 1.f);
    __syncthreads();
    if (tid < NPG) soffs[tid] = sstart[tid];
    __syncthreads();
    if (tid < EPG) {
        int pos = atomicAdd(&soffs[sde[tid]], 1);
        ssrt[pos] = se[tid];
    }
    // embedding gather (coalesced over tid); independent of CSR arrays
    float* hg = g_h + (size_t)g * NPG * H;
    for (int n = 0; n < NPG; n++) {
        float acc = 0.f;
        #pragma unroll
        for (int f = 0; f < 9; f++) {
            int v = sx[n*9 + f];
            acc += __ldg(&emb[((size_t)f*119 + v)*128 + tid]);
        }
        sh[n*H + tid] = acc;
        hg[(size_t)n*H + tid] = acc;
    }
    __syncthreads();
    float* mg = g_mean + (size_t)g * NPG * H;
    #pragma unroll 2
    for (int n = 0; n < NPG; n++) {
        float acc = 0.f;
        int b = sstart[n], e2 = sstart[n+1];
        for (int j = b; j < e2; j++) acc += sh[ssrt[j]*H + tid];
        mg[(size_t)n*H + tid] = acc * srdeg[n];
    }
}

// ================= K2: neighbor-mean via CSR counting sort (R7-proven, 102us) =================
__global__ __launch_bounds__(128)
void k_agg2(const int* __restrict__ ei) {
    __shared__ float sh[NPG * H];
    __shared__ int   se[EPG], sde[EPG], sdeg[NPG], sstart[NPG+1], soffs[NPG], ssrt[EPG];
    __shared__ float srdeg[NPG];
    const int g = blockIdx.x, tid = threadIdx.x;
    const float* hg = g_h + (size_t)g * NPG * H;
    for (int i = tid; i < NPG*32; i += 128)
        *(float4*)&sh[i*4] = *(const float4*)(hg + (size_t)i*4);
    if (tid < NPG) sdeg[tid] = 0;
    __syncthreads();
    if (tid < EPG) {
        int s = ei[(size_t)g*EPG + tid]                 - g*NPG;
        int d = ei[(size_t)NEDGE + (size_t)g*EPG + tid] - g*NPG;
        se[tid] = s; sde[tid] = d;
        atomicAdd(&sdeg[d], 1);
    }
    __syncthreads();
    if (tid == 0) {
        int acc = 0;
        #pragma unroll
        for (int n = 0; n < NPG; n++) { sstart[n] = acc; acc += sdeg[n]; }
        sstart[NPG] = acc;
    }
    if (tid < NPG) srdeg[tid] = 1.f / fmaxf((float)sdeg[tid], 1.f);
    __syncthreads();
    if (tid < NPG) soffs[tid] = sstart[tid];
    __syncthreads();
    if (tid < EPG) {
        int pos = atomicAdd(&soffs[sde[tid]], 1);
        ssrt[pos] = se[tid];
    }
    __syncthreads();
    float* mg = g_mean + (size_t)g * NPG * H;
    const int c = tid;
    #pragma unroll 2
    for (int n = 0; n < NPG; n++) {
        float acc = 0.f;
        int b = sstart[n], e2 = sstart[n+1];
        for (int j = b; j < e2; j++) acc += sh[ssrt[j]*H + c];
        mg[(size_t)n*H + c] = acc * srdeg[n];
    }
}

// ================= tf32 mma.sync helper (verified layout) =================
__device__ __forceinline__ void mma_tf32(float* d, const uint32_t* a,
                                         uint32_t b0, uint32_t b1) {
    asm volatile(
        "mma.sync.aligned.m16n8k8.row.col.f32.tf32.tf32.f32 "
        "{%0,%1,%2,%3}, {%4,%5,%6,%7}, {%8,%9}, {%0,%1,%2,%3};\n"
        : "+f"(d[0]), "+f"(d[1]), "+f"(d[2]), "+f"(d[3])
        : "r"(a[0]), "r"(a[1]), "r"(a[2]), "r"(a[3]), "r"(b0), "r"(b1));
}

#define WPITCH 132
#define TPITCH 17
#define WP2    132   // pipelined W chunk pitch
#define AP2    36    // pipelined A chunk pitch
#define PIPE_FLOATS (2*32*WP2 + 2*128*AP2)   // 17664 floats = 70656 B

// ================= K3a: pipelined tensor-core GEMM (R9-proven) =================
template<int RELU, int POOLED>
__global__ __launch_bounds__(256, 2)
void k_gemm_pipe(const float* __restrict__ Wl, const float* __restrict__ Wr,
                 const float* __restrict__ bl,
                 const float* __restrict__ bng, const float* __restrict__ bnb,
                 const float* __restrict__ bnm, const float* __restrict__ bnv)
{
    extern __shared__ float smem[];
    float* sWb0 = smem;
    float* sWb1 = smem + 32*WP2;
    float* sAb0 = smem + 2*32*WP2;
    float* sAb1 = smem + 2*32*WP2 + 128*AP2;
    __shared__ float sscale[128], sshift[128];

    const int tid  = threadIdx.x;
    const int row0 = blockIdx.x * 128;
    const float* Am = POOLED ? g_pm : g_mean;
    float*       Ah = POOLED ? g_x2 : g_h;

    if (tid < 128) {
        float sc = bng[tid] * rsqrtf(bnv[tid] + 1e-5f);
        sscale[tid] = sc;
        sshift[tid] = bnb[tid] + sc * (bl[tid] - bnm[tid]);
    }

    const int lane = tid & 31, warp = tid >> 5;
    const int gid = lane >> 2, tig = lane & 3;
    const int wr0 = (warp & 3) * 32;
    const int wc0 = (warp >> 2) * 64;
    float d[2][8][4] = {};

    auto issue = [&](int ch, float* sA, float* sW) {
        #pragma unroll
        for (int v = 0; v < 4; v++) {
            int i  = tid + v*256;
            int r  = i >> 3, c4 = (i & 7) * 4;
            int gk = ch*32 + c4;
            int grow = row0 + r;
            const float* ap;
            if (gk < 128) {
                int mrow = POOLED ? (grow / 7) : grow;
                ap = Am + (size_t)mrow*128 + gk;
            } else {
                ap = Ah + (size_t)grow*128 + (gk - 128);
            }
            uint32_t dst = (uint32_t)__cvta_generic_to_shared(&sA[r*AP2 + c4]);
            CP_ASYNC16(dst, ap);
        }
        #pragma unroll
        for (int v = 0; v < 4; v++) {
            int i  = tid + v*256;
            int r  = i >> 5, c4 = (i & 31) * 4;
            int gk = ch*32 + r;
            const float* wp = (gk < 128) ? (Wl + (size_t)gk*128 + c4)
                                         : (Wr + (size_t)(gk - 128)*128 + c4);
            uint32_t dst = (uint32_t)__cvta_generic_to_shared(&sW[r*WP2 + c4]);
            CP_ASYNC16(dst, wp);
        }
        CP_COMMIT();
    };

    issue(0, sAb0, sWb0);
    #pragma unroll
    for (int ch = 0; ch < 8; ch++) {
        if (ch < 7) issue(ch + 1, ((ch+1) & 1) ? sAb1 : sAb0,
                                   ((ch+1) & 1) ? sWb1 : sWb0);
        if (ch < 7) { CP_WAIT(1); } else { CP_WAIT(0); }
        __syncthreads();
        const float* sA = (ch & 1) ? sAb1 : sAb0;
        const float* sW = (ch & 1) ? sWb1 : sWb0;
        #pragma unroll
        for (int ks = 0; ks < 4; ks++) {
            const int kk = ks * 8;
            uint32_t a[2][4];
            #pragma unroll
            for (int mi = 0; mi < 2; mi++) {
                const float* ap = sA + (wr0 + mi*16 + gid)*AP2 + kk + tig;
                a[mi][0] = __float_as_uint(ap[0]);
                a[mi][1] = __float_as_uint(ap[8*AP2]);
                a[mi][2] = __float_as_uint(ap[4]);
                a[mi][3] = __float_as_uint(ap[8*AP2 + 4]);
            }
            const float* bp = sW + (kk + tig)*WP2 + wc0 + gid;
            #pragma unroll
            for (int nj = 0; nj < 8; nj++) {
                uint32_t b0 = __float_as_uint(bp[nj*8]);
                uint32_t b1 = __float_as_uint(bp[nj*8 + 4*WP2]);
                mma_tf32(d[0][nj], a[0], b0, b1);
                mma_tf32(d[1][nj], a[1], b0, b1);
            }
        }
        __syncthreads();
    }

    #pragma unroll
    for (int mi = 0; mi < 2; mi++)
        #pragma unroll
        for (int half = 0; half < 2; half++) {
            const int row = wr0 + mi*16 + gid + half*8;
            float* orow = Ah + (size_t)(row0 + row) * 128;
            #pragma unroll
            for (int nj = 0; nj < 8; nj++) {
                const int col = wc0 + nj*8 + tig*2;
                float2 res = *(float2*)(orow + col);
                float v0 = d[mi][nj][half*2 + 0] * sscale[col]     + sshift[col];
                float v1 = d[mi][nj][half*2 + 1] * sscale[col + 1] + sshift[col + 1];
                if (RELU) { v0 = fmaxf(v0, 0.f); v1 = fmaxf(v1, 0.f); }
                *(float2*)(orow + col) = make_float2(v0 + res.x, v1 + res.y);
            }
        }
}

// ================= K3b: pipelined GEMM + fused T epilogue (li=1) =================
// After the main loop the cp.async ring buffers are dead; h_final (128x132 =
// 67.6KB) overlays them (ring = 70.7KB) for the T = h_final @ [aWl|aWr] pass.
__global__ __launch_bounds__(256, 2)
void k_gemm_pipeT(const float* __restrict__ Wl, const float* __restrict__ Wr,
                  const float* __restrict__ bl,
                  const float* __restrict__ bng, const float* __restrict__ bnb,
                  const float* __restrict__ bnm, const float* __restrict__ bnv,
                  const float* __restrict__ aWl, const float* __restrict__ aWr)
{
    extern __shared__ float smem[];
    float* sWb0 = smem;
    float* sWb1 = smem + 32*WP2;
    float* sAb0 = smem + 2*32*WP2;
    float* sAb1 = smem + 2*32*WP2 + 128*AP2;
    float* sHf  = smem;                        // overlay: 128 x WPITCH after main loop
    __shared__ float sscale[128], sshift[128];
    __shared__ float sW2[128*TPITCH];

    const int tid  = threadIdx.x;
    const int row0 = blockIdx.x * 128;

    if (tid < 128) {
        float sc = bng[tid] * rsqrtf(bnv[tid] + 1e-5f);
        sscale[tid] = sc;
        sshift[tid] = bnb[tid] + sc * (bl[tid] - bnm[tid]);
    }
    for (int i = tid; i < 128*16; i += 256) {
        int k = i >> 4, c = i & 15;
        float v = 0.f;
        if (c < 7)       v = aWl[k*NCL + c];
        else if (c < 14) v = aWr[k*NCL + (c - 7)];
        sW2[k*TPITCH + c] = v;
    }

    const int lane = tid & 31, warp = tid >> 5;
    const int gid = lane >> 2, tig = lane & 3;
    const int wr0 = (warp & 3) * 32;
    const int wc0 = (warp >> 2) * 64;
    float d[2][8][4] = {};

    auto issue = [&](int ch, float* sA, float* sW) {
        #pragma unroll
        for (int v = 0; v < 4; v++) {
            int i  = tid + v*256;
            int r  = i >> 3, c4 = (i & 7) * 4;
            int gk = ch*32 + c4;
            int grow = row0 + r;
            const float* ap = (gk < 128) ? (g_mean + (size_t)grow*128 + gk)
                                         : (g_h    + (size_t)grow*128 + (gk - 128));
            uint32_t dst = (uint32_t)__cvta_generic_to_shared(&sA[r*AP2 + c4]);
            CP_ASYNC16(dst, ap);
        }
        #pragma unroll
        for (int v = 0; v < 4; v++) {
            int i  = tid + v*256;
            int r  = i >> 5, c4 = (i & 31) * 4;
            int gk = ch*32 + r;
            const float* wp = (gk < 128) ? (Wl + (size_t)gk*128 + c4)
                                         : (Wr + (size_t)(gk - 128)*128 + c4);
            uint32_t dst = (uint32_t)__cvta_generic_to_shared(&sW[r*WP2 + c4]);
            CP_ASYNC16(dst, wp);
        }
        CP_COMMIT();
    };

    issue(0, sAb0, sWb0);
    #pragma unroll
    for (int ch = 0; ch < 8; ch++) {
        if (ch < 7) issue(ch + 1, ((ch+1) & 1) ? sAb1 : sAb0,
                                   ((ch+1) & 1) ? sWb1 : sWb0);
        if (ch < 7) { CP_WAIT(1); } else { CP_WAIT(0); }
        __syncthreads();
        const float* sA = (ch & 1) ? sAb1 : sAb0;
        const float* sW = (ch & 1) ? sWb1 : sWb0;
        #pragma unroll
        for (int ks = 0; ks < 4; ks++) {
            const int kk = ks * 8;
            uint32_t a[2][4];
            #pragma unroll
            for (int mi = 0; mi < 2; mi++) {
                const float* ap = sA + (wr0 + mi*16 + gid)*AP2 + kk + tig;
                a[mi][0] = __float_as_uint(ap[0]);
                a[mi][1] = __float_as_uint(ap[8*AP2]);
                a[mi][2] = __float_as_uint(ap[4]);
                a[mi][3] = __float_as_uint(ap[8*AP2 + 4]);
            }
            const float* bp = sW + (kk + tig)*WP2 + wc0 + gid;
            #pragma unroll
            for (int nj = 0; nj < 8; nj++) {
                uint32_t b0 = __float_as_uint(bp[nj*8]);
                uint32_t b1 = __float_as_uint(bp[nj*8 + 4*WP2]);
                mma_tf32(d[0][nj], a[0], b0, b1);
                mma_tf32(d[1][nj], a[1], b0, b1);
            }
        }
        __syncthreads();   // last iteration: frees ring buffers for overlay
    }

    // epilogue: bn + relu + residual; write global AND the sHf overlay
    #pragma unroll
    for (int mi = 0; mi < 2; mi++)
        #pragma unroll
        for (int half = 0; half < 2; half++) {
            const int row = wr0 + mi*16 + gid + half*8;
            float* orow = g_h + (size_t)(row0 + row) * 128;
            #pragma unroll
            for (int nj = 0; nj < 8; nj++) {
                const int col = wc0 + nj*8 + tig*2;
                float2 res = *(float2*)(orow + col);
                float v0 = d[mi][nj][half*2 + 0] * sscale[col]     + sshift[col];
                float v1 = d[mi][nj][half*2 + 1] * sscale[col + 1] + sshift[col + 1];
                v0 = fmaxf(v0, 0.f); v1 = fmaxf(v1, 0.f);
                v0 += res.x; v1 += res.y;
                *(float2*)(orow + col) = make_float2(v0, v1);
                sHf[row*WPITCH + col]     = v0;
                sHf[row*WPITCH + col + 1] = v1;
            }
        }

    __syncthreads();
    // T = h_final(sHf) @ W2(sW2, 128x16); warp w owns rows [w*16, w*16+16)
    float dt[2][4] = {};
    #pragma unroll
    for (int ks = 0; ks < 16; ks++) {
        const int kk = ks * 8;
        uint32_t a[4];
        const float* ap = sHf + (warp*16 + gid)*WPITCH + kk + tig;
        a[0] = __float_as_uint(ap[0]);
        a[1] = __float_as_uint(ap[8*WPITCH]);
        a[2] = __float_as_uint(ap[4]);
        a[3] = __float_as_uint(ap[8*WPITCH + 4]);
        #pragma unroll
        for (int nt = 0; nt < 2; nt++) {
            uint32_t b0 = __float_as_uint(sW2[(kk + tig)*TPITCH     + nt*8 + gid]);
            uint32_t b1 = __float_as_uint(sW2[(kk + tig + 4)*TPITCH + nt*8 + gid]);
            mma_tf32(dt[nt], a, b0, b1);
        }
    }
    #pragma unroll
    for (int nt = 0; nt < 2; nt++)
        #pragma unroll
        for (int half = 0; half < 2; half++) {
            const int row = warp*16 + gid + half*8;
            const int col = nt*8 + tig*2;
            float* trow = g_t + (size_t)(row0 + row) * 14;
            if (col < 14)     trow[col]     = dt[nt][half*2 + 0];
            if (col + 1 < 14) trow[col + 1] = dt[nt][half*2 + 1];
        }
}

// ================= K4: per-graph logits-agg + softmax + pooling + losses + pm =================
__global__ void k_pool(const int* __restrict__ ei, const float* __restrict__ abl) {
    __shared__ float sh[NPG * H];
    __shared__ float t1[NPG*NCL], t2[NPG*NCL], ssl[NPG*NCL], sd[NPG*NCL];
    __shared__ float adj[NPG * NPG];
    __shared__ int   se[EPG], de[EPG], degi[NPG];
    __shared__ float red[128], red2[128];
    const int g = blockIdx.x, tid = threadIdx.x;  // 128
    const float* hg = g_h + (size_t)g * NPG * H;
    for (int i = tid; i < NPG * H; i += 128) sh[i] = hg[i];
    for (int i = tid; i < NPG * 14; i += 128) {
        int n = i / 14, c = i - n*14;
        float v = g_t[(size_t)g*NPG*14 + i];
        if (c < 7) t1[n*7 + c] = v; else t2[n*7 + (c-7)] = v;
    }
    for (int i = tid; i < NPG * NPG; i += 128) adj[i] = 0.f;
    for (int i = tid; i < NPG * NCL; i += 128) ssl[i] = 0.f;
    if (tid < NPG) degi[tid] = 0;
    if (tid < EPG) {
        se[tid] = ei[(size_t)g*EPG + tid]                 - g*NPG;
        de[tid] = ei[(size_t)NEDGE + (size_t)g*EPG + tid] - g*NPG;
    }
    __syncthreads();
    if (tid < EPG) {
        atomicAdd(&degi[de[tid]], 1);
        atomicAdd(&adj[se[tid]*NPG + de[tid]], 1.f);
        #pragma unroll
        for (int c = 0; c < NCL; c++)
            atomicAdd(&ssl[de[tid]*NCL + c], t1[se[tid]*NCL + c]);
    }
    __syncthreads();
    for (int i = tid; i < NPG * NCL; i += 128) {
        int n = i / NCL;
        ssl[i] = ssl[i] / fmaxf((float)degi[n], 1.f) + t2[i] + abl[i - n*NCL];
    }
    __syncthreads();
    float ent_local = 0.f;
    if (tid < NPG) {
        float v[NCL], mx = -1e30f;
        #pragma unroll
        for (int c = 0; c < NCL; c++) { v[c] = ssl[tid*NCL + c]; mx = fmaxf(mx, v[c]); }
        float s = 0.f;
        #pragma unroll
        for (int c = 0; c < NCL; c++) { v[c] = expf(v[c] - mx); s += v[c]; }
        float inv = 1.f / s;
        #pragma unroll
        for (int c = 0; c < NCL; c++) {
            float p = v[c] * inv;
            sd[tid*NCL + c] = p;
            ent_local += -p * logf(p + 1e-15f);
        }
    }
    __syncthreads();
    float* x2g = g_x2 + (size_t)g * NCL * H;
    float pmsum = 0.f;
    #pragma unroll
    for (int c = 0; c < NCL; c++) {
        float a = 0.f;
        #pragma unroll
        for (int n = 0; n < NPG; n++) a += sd[n*NCL + c] * sh[n*128 + tid];
        x2g[c*128 + tid] = a;
        pmsum += a;
    }
    g_pm[(size_t)g*128 + tid] = pmsum * (1.f / 7.f);
    float link_local = 0.f;
    for (int p = tid; p < NPG * NPG; p += 128) {
        int n = p / NPG, m = p - NPG*n;
        float ss = 0.f;
        #pragma unroll
        for (int c = 0; c < NCL; c++) ss += sd[n*NCL + c] * sd[m*NCL + c];
        float dd = adj[p] - ss;
        link_local += dd * dd;
    }
    red[tid] = link_local; red2[tid] = ent_local;
    __syncthreads();
    for (int s = 64; s > 0; s >>= 1) {
        if (tid < s) { red[tid] += red[tid + s]; red2[tid] += red2[tid + s]; }
        __syncthreads();
    }
    if (tid == 0) { g_linkpart[g] = red[0]; g_entpart[g] = red2[0]; }
}

// ================= K5: per-graph mean of clusters (for li=3) =================
__global__ void k_pmean() {
    int idx = blockIdx.x * 256 + threadIdx.x;
    int g = idx >> 7, col = idx & 127;
    const float* xg = g_x2 + (size_t)g * NCL * H + col;
    float a = 0.f;
    #pragma unroll
    for (int c = 0; c < NCL; c++) a += xg[c * 128];
    g_pm[idx] = a * (1.f / 7.f);
}

// ================= K6: readout =================
__global__ void k_readout(const float* __restrict__ linW, const float* __restrict__ linb,
                          float* __restrict__ out) {
    const int g = blockIdx.x, tid = threadIdx.x;  // 128
    const float* xg = g_x2 + (size_t)g * NCL * H;
    float v = 0.f;
    #pragma unroll
    for (int c = 0; c < NCL; c++) v += xg[c * 128 + tid];
    v *= (1.f / 7.f);
    __shared__ float red[128];
    red[tid] = v * linW[tid];
    __syncthreads();
    for (int s = 64; s > 0; s >>= 1) {
        if (tid < s) red[tid] += red[tid + s];
        __syncthreads();
    }
    if (tid == 0) out[g] = 1.f / (1.f + expf(-(red[0] + linb[0])));
}

// ================= K7: deterministic loss reduction =================
__global__ void k_reduce(float* __restrict__ out) {
    __shared__ float s1[1024], s2[1024];
    const int tid = threadIdx.x;
    float a = 0.f, b = 0.f;
    for (int i = tid; i < NB; i += 1024) { a += g_linkpart[i]; b += g_entpart[i]; }
    s1[tid] = a; s2[tid] = b;
    __syncthreads();
    for (int s = 512; s > 0; s >>= 1) {
        if (tid < s) { s1[tid] += s1[tid + s]; s2[tid] += s2[tid + s]; }
        __syncthreads();
    }
    if (tid == 0) {
        out[NB]     = sqrtf(s1[0]) / 11075584.f;   // nb * 26 * 26
        out[NB + 1] = s2[0] / (float)NTOT;
    }
}

extern "C" void kernel_launch(void* const* d_in, const int* in_sizes, int n_in,
                              void* d_out, int out_size) {
    (void)in_sizes; (void)n_in; (void)out_size;
    const int*   x    = (const int*)  d_in[0];
    const int*   ei   = (const int*)  d_in[1];
    const float* emb  = (const float*)d_in[3];
    const float* cWl  = (const float*)d_in[4];
    const float* cbl  = (const float*)d_in[5];
    const float* cWr  = (const float*)d_in[6];
    const float* bng  = (const float*)d_in[7];
    const float* bnb  = (const float*)d_in[8];
    const float* bnm  = (const float*)d_in[9];
    const float* bnv  = (const float*)d_in[10];
    const float* aWl  = (const float*)d_in[11];
    const float* abl  = (const float*)d_in[12];
    const float* aWr  = (const float*)d_in[13];
    const float* linW = (const float*)d_in[14];
    const float* linb = (const float*)d_in[15];
    float* out = (float*)d_out;

    const int pipe_smem = PIPE_FLOATS * 4;   // 70656
    cudaFuncSetAttribute(k_gemm_pipe<1,0>, cudaFuncAttributeMaxDynamicSharedMemorySize, pipe_smem);
    cudaFuncSetAttribute(k_gemm_pipe<0,1>, cudaFuncAttributeMaxDynamicSharedMemorySize, pipe_smem);
    cudaFuncSetAttribute(k_gemm_pipeT, cudaFuncAttributeMaxDynamicSharedMemorySize, pipe_smem);

    // layer 0 (encoder fused with aggregation)
    k_encagg<<<NB, 128>>>(x, emb, ei);
    k_gemm_pipe<1,0><<<NTOT / 128, 256, pipe_smem>>>(
        cWl, cWr, cbl, bng, bnb, bnm, bnv);
    // layer 1 (+ fused T = h@[aWl|aWr])
    k_agg2<<<NB, 128>>>(ei);
    k_gemm_pipeT<<<NTOT / 128, 256, pipe_smem>>>(
        cWl + 16384, cWr + 16384, cbl + 128,
        bng + 128, bnb + 128, bnm + 128, bnv + 128, aWl, aWr);

    k_pool<<<NB, 128>>>(ei, abl);     // also writes g_pm (first pmean fused)

    // pooled layer 2
    k_gemm_pipe<0,1><<<NB * NCL / 128, 256, pipe_smem>>>(
        cWl + 2*16384, cWr + 2*16384, cbl + 2*128,
        bng + 2*128, bnb + 2*128, bnm + 2*128, bnv + 2*128);
    // pooled layer 3
    k_pmean<<<NB * 128 / 256, 256>>>();
    k_gemm_pipe<0,1><<<NB * NCL / 128, 256, pipe_smem>>>(
        cWl + 3*16384, cWr + 3*16384, cbl + 3*128,
        bng + 3*128, bnb + 3*128, bnm + 3*128, bnv + 3*128);

    k_readout<<<NB, 128>>>(linW, linb, out);
    k_reduce<<<1, 1024>>>(out);
}